// round 7
// baseline (speedup 1.0000x reference)
#include <cuda_runtime.h>
#include <math.h>

namespace {
constexpr int B = 256, T = 64, S = 10, H = 128, IPT = 128, Q = 128;
constexpr int ROWLEN = 2 + IPT;
constexpr int HH = H * H;
constexpr long long HSEQ_ELEMS = (long long)B * T * S * H;
constexpr long long HC_ELEMS   = (long long)B * S * H;
// dynamic smem layout (float offsets) — W1/W2 evicted to global
constexpr int SM_W3  = 0;                   // [128][128]
constexpr int SM_HT  = SM_W3 + HH;          // [128][12]
constexpr int SM_BUF = SM_HT + H * 12;      // [128][12]
constexpr int SM_QPS = SM_BUF + H * 12;     // [10][128]
constexpr int SM_SSM = SM_QPS + S * H;      // [10][64]
constexpr int SM_ST2 = SM_SSM + S * T;      // [10][128]
constexpr int SM_ST3 = SM_ST2 + S * H;      // [10][128]
constexpr int SM_ATS = SM_ST3 + S * H;      // [6][128]
constexpr int SM_RED = SM_ATS + 6 * H;      // [8]
constexpr int SM_TOTAL = SM_RED + 8;        // 24712 floats = 98848 B -> 2 CTAs/SM
}

// ---------------- scratch ----------------
__device__ float g_qp[B * T * S * H];
__device__ float g_A [B * T * 6 * H];
__device__ float g_pk[B * T * S * H];
__device__ float g_pv[B * T * S * H];
__device__ float g_Wc[H * H];
__device__ float g_bc[H];
__device__ float2 g_Wh01[H * H];        // interleaved gates 0,1
__device__ float2 g_Wh23[H * H];        // interleaved gates 2,3
__device__ float g_nvinv[T];
__device__ float g_losspart[B];
__device__ int   g_perm[B];

// ---------------- f32x2 helpers ----------------
using u64 = unsigned long long;
__device__ __forceinline__ u64 pk2(float lo, float hi) {
    u64 r; asm("mov.b64 %0,{%1,%2};" : "=l"(r) : "f"(lo), "f"(hi)); return r;
}
__device__ __forceinline__ u64 dup2(float x) { return pk2(x, x); }
__device__ __forceinline__ void un2(u64 v, float& a, float& b) {
    asm("mov.b64 {%0,%1},%2;" : "=f"(a), "=f"(b) : "l"(v));
}
__device__ __forceinline__ void fma2(u64& d, u64 a, u64 b) {
    asm("fma.rn.f32x2 %0,%1,%2,%0;" : "+l"(d) : "l"(a), "l"(b));
}

__device__ __forceinline__ float sigf(float x) {
    return __fdividef(1.f, 1.f + __expf(-x));
}
__device__ __forceinline__ float tanhfast(float x) {
    return __fdividef(2.f, 1.f + __expf(-2.f * x)) - 1.f;
}

// ---------------- fold: q-weights + Wh interleave + perm/nvinv ----------------
__global__ void __launch_bounds__(128) fold_kernel(
    const float* __restrict__ Wa, const float* __restrict__ ba,
    const float* __restrict__ Wattn, const float* __restrict__ battn,
    const float* __restrict__ Wh, const int* __restrict__ keys_length)
{
    const int bx = blockIdx.x, tid = threadIdx.x;
    if (bx < 128) {
        const int q = bx, h = tid;
        const float scale = 0.08838834764831845f;
        float acc = 0.f;
        for (int j = 0; j < H; ++j) acc += Wa[q * H + j] * Wattn[j * H + h];
        g_Wc[q * H + h] = acc * scale;
        if (q == 0) {
            float bacc = battn[h];
            for (int j = 0; j < H; ++j) bacc += ba[j] * Wattn[j * H + h];
            g_bc[h] = bacc * scale;
        }
        return;
    }
    const int e = (bx - 128) * 128 + tid;
    g_Wh01[e] = make_float2(Wh[e], Wh[HH + e]);
    g_Wh23[e] = make_float2(Wh[2 * HH + e], Wh[3 * HH + e]);

    if (bx == 128) {
#pragma unroll
        for (int half = 0; half < 2; ++half) {
            const int b = tid + half * 128;
            const int kb = keys_length[b];
            int rank = 0;
            for (int j = 0; j < B; ++j) {
                const int kj = keys_length[j];
                rank += (kj > kb) || (kj == kb && j < b);
            }
            g_perm[rank] = b;
        }
        if (tid < T) {
            int cnt = 0;
            for (int j = 0; j < B; ++j) cnt += (tid < keys_length[j]) ? 1 : 0;
            g_nvinv[tid] = cnt ? 1.f / (float)cnt : 0.f;
        }
    }
}

// ---------------- precompute A[B,T,6,H] (only t < kl) ----------------
__global__ void __launch_bounds__(128) pre_kernel(
    const float* __restrict__ inputs, const float* __restrict__ Wx,
    const float* __restrict__ Wts, const float* __restrict__ bg,
    const int* __restrict__ keys_length)
{
    const int b = blockIdx.x, k = threadIdx.x;
    const int kl = keys_length[b];
    if (kl == 0) return;
    __shared__ float xsT[IPT][66];
    __shared__ float Tts[T], Dts[T];
    const int tmax = kl;
    for (int idx = k; idx < tmax * IPT; idx += 128) {
        const int t = idx >> 7, i = idx & 127;
        xsT[i][t] = inputs[(long long)(b * T + t) * ROWLEN + 2 + i];
    }
    if (k < tmax) {
        Tts[k] = inputs[(long long)(b * T + k) * ROWLEN + 0];
        Dts[k] = inputs[(long long)(b * T + k) * ROWLEN + 1];
    }
    __syncthreads();

    const float wt0 = Wts[0 * H + k], wt1 = Wts[1 * H + k];
    const float wt2 = Wts[2 * H + k], wt3 = Wts[3 * H + k];
    const float wt4 = Wts[4 * H + k], wt5 = Wts[5 * H + k];
    float bgv[8];
#pragma unroll
    for (int g = 0; g < 8; ++g) bgv[g] = bg[g * H + k];

    float* Ab = g_A + ((long long)b * T * 6) * H + k;

    for (int t0 = 0; t0 < tmax; t0 += 16) {
        const int nt = min(16, tmax - t0);
        float T1v[16], T2v[16];
#pragma unroll
        for (int g = 0; g < 8; ++g) {
            u64 acc[8];
#pragma unroll
            for (int j = 0; j < 8; ++j) acc[j] = 0ull;
            const float* Wg = Wx + (long long)g * IPT * H + k;
#pragma unroll 4
            for (int i = 0; i < IPT; ++i) {
                const u64 wd = dup2(Wg[(long long)i * H]);
#pragma unroll
                for (int j = 0; j < 8; ++j)
                    fma2(acc[j], *(const u64*)&xsT[i][t0 + 2 * j], wd);
            }
#pragma unroll
            for (int j = 0; j < 8; ++j) {
                float v0, v1; un2(acc[j], v0, v1);
#pragma unroll
                for (int half = 0; half < 2; ++half) {
                    const int tt = 2 * j + half;
                    if (tt >= nt) continue;
                    const int t = t0 + tt;
                    const float v = half ? v1 : v0;
                    float* At = Ab + (long long)t * 6 * H;
                    if (g == 0)      At[0]     = v + bgv[0];
                    else if (g == 1) At[H]     = v + bgv[1];
                    else if (g == 2) At[2 * H] = v + bgv[2];
                    else if (g == 3) At[3 * H] = v + Tts[t] * wt4 + Dts[t] * wt5 + bgv[3];
                    else if (g == 4) T1v[tt] = sigf(v + sigf(Tts[t] * wt0) + bgv[4]);
                    else if (g == 5) T2v[tt] = sigf(v + sigf(Tts[t] * wt1) + bgv[5]);
                    else if (g == 6) At[4 * H] = T1v[tt] * sigf(v + sigf(Dts[t] * wt2) + bgv[6]);
                    else             At[5 * H] = T2v[tt] * sigf(v + sigf(Dts[t] * wt3) + bgv[7]);
                }
            }
        }
    }
}

// ---------------- qp = x_q @ Wc + bc (only 1 <= t < kl) ----------------
__global__ void __launch_bounds__(128) qp_kernel(
    const float* __restrict__ x_q, const int* __restrict__ keys_length)
{
    const int bt = blockIdx.x, k = threadIdx.x;
    const int b = bt >> 6, t = bt & 63;
    if (t == 0 || t >= keys_length[b]) return;
    __shared__ float xqT[Q][12];
    const float* xp = x_q + (long long)bt * S * Q;
    for (int idx = k; idx < S * Q; idx += 128) {
        const int s = idx >> 7, q = idx & 127;
        xqT[q][s] = xp[idx];
    }
    __syncthreads();
    const float bcv = g_bc[k];
    u64 acc[5];
#pragma unroll
    for (int p = 0; p < 5; ++p) acc[p] = dup2(bcv);
#pragma unroll 4
    for (int i = 0; i < Q; ++i) {
        const u64 wd = dup2(g_Wc[i * H + k]);
#pragma unroll
        for (int p = 0; p < 5; ++p)
            fma2(acc[p], *(const u64*)&xqT[i][2 * p], wd);
    }
    float* o = g_qp + (long long)bt * S * H + k;
#pragma unroll
    for (int p = 0; p < 5; ++p) {
        float v0, v1; un2(acc[p], v0, v1);
        o[(2 * p) * H] = v0; o[(2 * p + 1) * H] = v1;
    }
}

// ---------------- recurrent kernel: 256 threads, 2 CTAs/SM ----------------
__global__ void __launch_bounds__(256, 2) rec_kernel(
    const float* __restrict__ Wattn, const float* __restrict__ battn,
    const float* __restrict__ austgn_y, const int* __restrict__ keys_length,
    float* __restrict__ out)
{
    extern __shared__ float sm[];
    const int tid = threadIdx.x;
    const int k = tid & 127, half = tid >> 7;
    const int lane = tid & 31, warp = tid >> 5;
    // anti-correlated pairing: bid and bid+148 share an SM (classic placement);
    // give them ranks r and 255-r so per-SM work is ~constant.
    const int bid = blockIdx.x;
    const int rank = (bid < 148) ? bid : (403 - bid);
    const int b = g_perm[rank];
    const int kl = keys_length[b];

    // preload W3 into smem
    {
        const float4* src = (const float4*)(Wattn + 3 * HH);
        float4* dst = (float4*)(sm + SM_W3);
        for (int i = tid; i < HH / 4; i += 256) dst[i] = src[i];
    }
    for (int i = tid; i < 2 * H * 12; i += 256) sm[SM_HT + i] = 0.f;
    __syncthreads();

    float* hT   = sm + SM_HT;
    float* bufT = sm + SM_BUF;

    const float b1v = battn[1 * H + k];
    const float b2v = battn[2 * H + k];
    const float b3v = battn[3 * H + k];

    float c[S];
#pragma unroll
    for (int s = 0; s < S; ++s) c[s] = 0.f;
    float lossacc = 0.f;

    int t = 0;
    for (; t < kl; ++t) {
        // ---- phase A: prefetch cell inputs (half0) + load qp ----
        float a0 = 0.f, a1 = 0.f, a2 = 0.f, a3 = 0.f, td1 = 0.f, td2 = 0.f, yv = 0.f, nvv = 0.f;
        if (half == 0) {
            const float* Ab = g_A + ((long long)((b * T + t) * 6)) * H + k;
            a0 = Ab[0]; a1 = Ab[H]; a2 = Ab[2 * H]; a3 = Ab[3 * H];
            td1 = Ab[4 * H]; td2 = Ab[5 * H];
            yv = austgn_y[b * T + t]; nvv = g_nvinv[t];
        }
        if (t > 0) {
            const float* qpp = g_qp + ((long long)(b * T + t) * S) * H;
#pragma unroll
            for (int j = 0; j < 5; ++j) {
                const int s = half * 5 + j;
                sm[SM_QPS + s * H + k] = qpp[s * H + k];
            }
        }
        __syncthreads();

        if (t > 0) {
            // ---- phase B: scores, octet (8 lanes) per dot ----
            const int nd = S * t;
            const int group = tid >> 3, gl = tid & 7;
            const int iters = (nd + 31) >> 5;
            for (int i = 0; i < iters; ++i) {
                const int idx = group + 32 * i;
                const bool valid = idx < nd;
                int s = 0, tp = 0;
                float acc = 0.f;
                if (valid) {
                    s = idx / t; tp = idx - s * t;
                    const float4* pkr = (const float4*)(g_pk + ((long long)((b * T + tp) * S + s)) * H) + gl * 4;
                    const float4* qr  = (const float4*)(sm + SM_QPS + s * H) + gl * 4;
#pragma unroll
                    for (int j = 0; j < 4; ++j) {
                        const float4 q = qr[j], p = pkr[j];
                        acc += q.x * p.x + q.y * p.y + q.z * p.z + q.w * p.w;
                    }
                }
                acc += __shfl_xor_sync(0xffffffffu, acc, 1);
                acc += __shfl_xor_sync(0xffffffffu, acc, 2);
                acc += __shfl_xor_sync(0xffffffffu, acc, 4);
                if (valid && gl == 0) sm[SM_SSM + s * T + tp] = acc;
            }
            __syncthreads();

            // ---- phase C: softmax per s over 8 warps ----
            for (int s = warp; s < S; s += 8) {
                float* row = sm + SM_SSM + s * T;
                float mx = -1e30f;
                for (int tp = lane; tp < t; tp += 32) mx = fmaxf(mx, row[tp]);
#pragma unroll
                for (int o = 16; o > 0; o >>= 1) mx = fmaxf(mx, __shfl_xor_sync(0xffffffffu, mx, o));
                float sum = 0.f;
                for (int tp = lane; tp < t; tp += 32) {
                    const float e = __expf(row[tp] - mx);
                    row[tp] = e; sum += e;
                }
#pragma unroll
                for (int o = 16; o > 0; o >>= 1) sum += __shfl_xor_sync(0xffffffffu, sum, o);
                const float inv = __fdividef(1.f, sum);
                for (int tp = lane; tp < t; tp += 32) row[tp] *= inv;
            }
            __syncthreads();

            // ---- phase D: ctx, s-split 4/6 ----
            if (half == 0) {
                float cx[4] = {0.f, 0.f, 0.f, 0.f};
                const float* pvb = g_pv + ((long long)b * T * S) * H + k;
#pragma unroll 4
                for (int tp = 0; tp < t; ++tp) {
                    const float* pvr = pvb + (long long)tp * S * H;
#pragma unroll
                    for (int s = 0; s < 4; ++s) cx[s] += sm[SM_SSM + s * T + tp] * pvr[s * H];
                }
#pragma unroll
                for (int s = 0; s < 4; ++s) bufT[k * 12 + s] = cx[s];
            } else {
                float cx[6] = {0.f, 0.f, 0.f, 0.f, 0.f, 0.f};
                const float* pvb = g_pv + ((long long)b * T * S) * H + k + 4 * H;
#pragma unroll 4
                for (int tp = 0; tp < t; ++tp) {
                    const float* pvr = pvb + (long long)tp * S * H;
#pragma unroll
                    for (int s = 0; s < 6; ++s) cx[s] += sm[SM_SSM + (s + 4) * T + tp] * pvr[s * H];
                }
#pragma unroll
                for (int s = 0; s < 6; ++s) bufT[k * 12 + 4 + s] = cx[s];
            }
            __syncthreads();
        }

        // ---- phase E: combined gate + at GEMMs ----
        u64 A0[5], A1[5], At2[2];     // half0
        if (half == 0) {
#pragma unroll
            for (int p = 0; p < 5; ++p) { A0[p] = 0ull; A1[p] = 0ull; }
            At2[0] = dup2(b3v); At2[1] = dup2(b3v);
            const float2* Wp = g_Wh01 + k;
#pragma unroll 4
            for (int h = 0; h < H; ++h) {
                const float2 w01 = Wp[h * H];
                const u64 w0 = dup2(w01.x);
                const u64 w1 = dup2(w01.y);
                const u64 w3 = dup2(sm[SM_W3 + h * H + k]);
                const float* hr = hT + h * 12;
                const float* br = bufT + h * 12;
#pragma unroll
                for (int p = 0; p < 5; ++p) {
                    const u64 hp = *(const u64*)(hr + 2 * p);
                    fma2(A0[p], hp, w0); fma2(A1[p], hp, w1);
                }
                fma2(At2[0], *(const u64*)(br),     w3);
                fma2(At2[1], *(const u64*)(br + 2), w3);
            }
        } else {
            u64 A2[5], A3[5], At3[3];
#pragma unroll
            for (int p = 0; p < 5; ++p) { A2[p] = 0ull; A3[p] = 0ull; }
#pragma unroll
            for (int j = 0; j < 3; ++j) At3[j] = dup2(b3v);
            const float2* Wp = g_Wh23 + k;
#pragma unroll 4
            for (int h = 0; h < H; ++h) {
                const float2 w23 = Wp[h * H];
                const u64 w2  = dup2(w23.x);
                const u64 w3g = dup2(w23.y);
                const u64 w3a = dup2(sm[SM_W3 + h * H + k]);
                const float* hr = hT + h * 12;
                const float* br = bufT + h * 12;
#pragma unroll
                for (int p = 0; p < 5; ++p) {
                    const u64 hp = *(const u64*)(hr + 2 * p);
                    fma2(A2[p], hp, w2); fma2(A3[p], hp, w3g);
                }
#pragma unroll
                for (int j = 0; j < 3; ++j)
                    fma2(At3[j], *(const u64*)(br + 4 + 2 * j), w3a);
            }
#pragma unroll
            for (int p = 0; p < 5; ++p) {
                float v0, v1;
                un2(A2[p], v0, v1);
                sm[SM_ST2 + (2 * p) * H + k] = v0; sm[SM_ST2 + (2 * p + 1) * H + k] = v1;
                un2(A3[p], v0, v1);
                sm[SM_ST3 + (2 * p) * H + k] = v0; sm[SM_ST3 + (2 * p + 1) * H + k] = v1;
            }
#pragma unroll
            for (int j = 0; j < 3; ++j) {
                float v0, v1; un2(At3[j], v0, v1);
                sm[SM_ATS + (2 * j) * H + k] = v0; sm[SM_ATS + (2 * j + 1) * H + k] = v1;
            }
        }
        __syncthreads();

        // ---- phase F: cell (half0 only) ----
        if (half == 0) {
            float G0[S], G1[S], at0[4];
#pragma unroll
            for (int p = 0; p < 5; ++p) {
                un2(A0[p], G0[2 * p], G0[2 * p + 1]);
                un2(A1[p], G1[2 * p], G1[2 * p + 1]);
            }
            un2(At2[0], at0[0], at0[1]);
            un2(At2[1], at0[2], at0[3]);
            float bsum = 0.f;
#pragma unroll
            for (int s = 0; s < S; ++s) {
                const float g2 = sm[SM_ST2 + s * H + k];
                const float g3 = sm[SM_ST3 + s * H + k];
                float atv = 1.f;
                if (t > 0) atv = (s < 4) ? at0[s] : sm[SM_ATS + (s - 4) * H + k];
                const float it = sigf(a0 + G0[s]);
                const float ft = sigf(a1 + G1[s]);
                const float ct = tanhfast(a2 + g2);
                const float ot = sigf(a3 + g3);
                const float itp = it * atv, ftp = ft * atv;
                const float fc = ftp * c[s];
                const float ic = itp * ct;
                const float chat = fc + ic * td1;
                c[s] = fc + ic * td2;
                const float hn = ot * tanhfast(chat);
                hT[k * 12 + s] = hn;
                const float p = fminf(fmaxf(hn, 1e-7f), 1.f - 1e-7f);
                bsum += -(yv * __logf(p) + (1.f - yv) * __logf(1.f - p));
            }
            lossacc += bsum * nvv;
        }
        __syncthreads();

        // ---- phase G: pk / pv GEMMs (weights from global, coalesced) ----
        if (half == 0) {
            u64 P[5];
#pragma unroll
            for (int p = 0; p < 5; ++p) P[p] = dup2(b1v);
            const float* W1g = Wattn + HH + k;
#pragma unroll 4
            for (int h = 0; h < H; ++h) {
                const u64 w = dup2(W1g[h * H]);
                const float* hr = hT + h * 12;
#pragma unroll
                for (int p = 0; p < 5; ++p)
                    fma2(P[p], *(const u64*)(hr + 2 * p), w);
            }
            float* pkp = g_pk + ((long long)((b * T + t) * S)) * H + k;
#pragma unroll
            for (int p = 0; p < 5; ++p) {
                float v0, v1; un2(P[p], v0, v1);
                pkp[(2 * p) * H] = v0; pkp[(2 * p + 1) * H] = v1;
            }
        } else {
            u64 P[5];
#pragma unroll
            for (int p = 0; p < 5; ++p) P[p] = dup2(b2v);
            const float* W2g = Wattn + 2 * HH + k;
#pragma unroll 4
            for (int h = 0; h < H; ++h) {
                const u64 w = dup2(W2g[h * H]);
                const float* hr = hT + h * 12;
#pragma unroll
                for (int p = 0; p < 5; ++p)
                    fma2(P[p], *(const u64*)(hr + 2 * p), w);
            }
            float* pvp = g_pv + ((long long)((b * T + t) * S)) * H + k;
#pragma unroll
            for (int p = 0; p < 5; ++p) {
                float v0, v1; un2(P[p], v0, v1);
                pvp[(2 * p) * H] = v0; pvp[(2 * p + 1) * H] = v1;
            }
            float* outp = out + ((long long)((b * T + t) * S)) * H + k;
#pragma unroll
            for (int s = 0; s < S; ++s) outp[s * H] = hT[k * 12 + s];
        }
        __syncthreads();
    }

    // masked steps: zeros
    for (; t < T; ++t) {
        float* outp = out + ((long long)((b * T + t) * S)) * H + k;
#pragma unroll
        for (int j = 0; j < 5; ++j) outp[(half * 5 + j) * H] = 0.f;
    }

    // final h, c
    if (half == 0) {
        float* oh = out + HSEQ_ELEMS + ((long long)b * S) * H + k;
#pragma unroll
        for (int s = 0; s < S; ++s) oh[s * H] = hT[k * 12 + s];
        float* oc = oh + HC_ELEMS;
#pragma unroll
        for (int s = 0; s < S; ++s) oc[s * H] = c[s];
    }

    // loss partial
    float v = (half == 0) ? lossacc : 0.f;
#pragma unroll
    for (int o = 16; o > 0; o >>= 1) v += __shfl_xor_sync(0xffffffffu, v, o);
    if (lane == 0) sm[SM_RED + warp] = v;
    __syncthreads();
    if (tid == 0) {
        float sum = 0.f;
#pragma unroll
        for (int w = 0; w < 8; ++w) sum += sm[SM_RED + w];
        g_losspart[b] = sum * (1.f / (float)(S * H));
    }
}

// ---------------- final loss reduction ----------------
__global__ void loss_kernel(float* __restrict__ out)
{
    __shared__ float smr[B];
    smr[threadIdx.x] = g_losspart[threadIdx.x];
    __syncthreads();
    for (int off = B / 2; off > 0; off >>= 1) {
        if (threadIdx.x < off) smr[threadIdx.x] += smr[threadIdx.x + off];
        __syncthreads();
    }
    if (threadIdx.x == 0) out[HSEQ_ELEMS + 2 * HC_ELEMS] = smr[0];
}

// ---------------- launch ----------------
extern "C" void kernel_launch(void* const* d_in, const int* in_sizes, int n_in,
                              void* d_out, int out_size)
{
    (void)in_sizes; (void)n_in; (void)out_size;
    const float* inputs      = (const float*)d_in[0];
    const float* x_q         = (const float*)d_in[1];
    const float* austgn_y    = (const float*)d_in[2];
    const int*   keys_length = (const int*)  d_in[3];
    const float* Wx          = (const float*)d_in[4];
    const float* Wh          = (const float*)d_in[5];
    const float* Wts         = (const float*)d_in[6];
    const float* bg          = (const float*)d_in[7];
    const float* Wa          = (const float*)d_in[8];
    const float* ba          = (const float*)d_in[9];
    const float* Wattn       = (const float*)d_in[10];
    const float* battn       = (const float*)d_in[11];
    float* out = (float*)d_out;

    static int smem_set = 0;
    if (!smem_set) {
        cudaFuncSetAttribute(rec_kernel, cudaFuncAttributeMaxDynamicSharedMemorySize,
                             SM_TOTAL * (int)sizeof(float));
        smem_set = 1;
    }

    fold_kernel<<<256, 128>>>(Wa, ba, Wattn, battn, Wh, keys_length);
    pre_kernel<<<B, 128>>>(inputs, Wx, Wts, bg, keys_length);
    qp_kernel<<<B * T, 128>>>(x_q, keys_length);
    rec_kernel<<<B, 256, SM_TOTAL * (int)sizeof(float)>>>(
        Wattn, battn, austgn_y, keys_length, out);
    loss_kernel<<<1, B>>>(out);
}

// round 9
// speedup vs baseline: 1.1364x; 1.1364x over previous
#include <cuda_runtime.h>
#include <math.h>

namespace {
constexpr int B = 256, T = 64, S = 10, H = 128, IPT = 128, Q = 128;
constexpr int ROWLEN = 2 + IPT;
constexpr int HH = H * H;
constexpr long long HSEQ_ELEMS = (long long)B * T * S * H;
constexpr long long HC_ELEMS   = (long long)B * S * H;
// dynamic smem layout (float offsets) — weights resident
constexpr int SM_W1  = 0;
constexpr int SM_W2  = SM_W1 + HH;
constexpr int SM_W3  = SM_W2 + HH;
constexpr int SM_HT  = SM_W3 + HH;          // [128][12]
constexpr int SM_BUF = SM_HT + H * 12;      // [128][12]
constexpr int SM_QPS = SM_BUF + H * 12;     // [10][128]
constexpr int SM_SSM = SM_QPS + S * H;      // [10][64]
constexpr int SM_ST2 = SM_SSM + S * T;      // [10][128]
constexpr int SM_ST3 = SM_ST2 + S * H;      // [10][128]
constexpr int SM_ATS = SM_ST3 + S * H;      // [6][128]
constexpr int SM_TOTAL = SM_ATS + 6 * H;    // 57472 floats = 229888 B
}

// ---------------- scratch ----------------
__device__ float g_qp[B * T * S * H];
__device__ float g_A [B * T * 6 * H];
__device__ float g_pk[B * T * S * H];
__device__ float g_pv[B * T * S * H];
__device__ float g_Wc[H * H];
__device__ float g_bc[H];
__device__ float2 g_Wh01[H * H];        // interleaved gates 0,1
__device__ float2 g_Wh23[H * H];        // interleaved gates 2,3
__device__ float g_nvinv[T];
__device__ float g_lpart[B * T];        // per-(b,t) loss partials
__device__ int   g_perm[B];

// ---------------- f32x2 helpers ----------------
using u64 = unsigned long long;
__device__ __forceinline__ u64 pk2(float lo, float hi) {
    u64 r; asm("mov.b64 %0,{%1,%2};" : "=l"(r) : "f"(lo), "f"(hi)); return r;
}
__device__ __forceinline__ u64 dup2(float x) { return pk2(x, x); }
__device__ __forceinline__ void un2(u64 v, float& a, float& b) {
    asm("mov.b64 {%0,%1},%2;" : "=f"(a), "=f"(b) : "l"(v));
}
__device__ __forceinline__ void fma2(u64& d, u64 a, u64 b) {
    asm("fma.rn.f32x2 %0,%1,%2,%0;" : "+l"(d) : "l"(a), "l"(b));
}

__device__ __forceinline__ float sigf(float x) {
    return __fdividef(1.f, 1.f + __expf(-x));
}
__device__ __forceinline__ float tanhfast(float x) {
    return __fdividef(2.f, 1.f + __expf(-2.f * x)) - 1.f;
}

// ---------------- fold: q-weights + Wh interleave + perm/nvinv ----------------
__global__ void __launch_bounds__(128) fold_kernel(
    const float* __restrict__ Wa, const float* __restrict__ ba,
    const float* __restrict__ Wattn, const float* __restrict__ battn,
    const float* __restrict__ Wh, const int* __restrict__ keys_length)
{
    const int bx = blockIdx.x, tid = threadIdx.x;
    if (bx < 128) {
        const int q = bx, h = tid;
        const float scale = 0.08838834764831845f;
        float acc = 0.f;
        for (int j = 0; j < H; ++j) acc += Wa[q * H + j] * Wattn[j * H + h];
        g_Wc[q * H + h] = acc * scale;
        if (q == 0) {
            float bacc = battn[h];
            for (int j = 0; j < H; ++j) bacc += ba[j] * Wattn[j * H + h];
            g_bc[h] = bacc * scale;
        }
        return;
    }
    const int e = (bx - 128) * 128 + tid;
    g_Wh01[e] = make_float2(Wh[e], Wh[HH + e]);
    g_Wh23[e] = make_float2(Wh[2 * HH + e], Wh[3 * HH + e]);

    if (bx == 128) {
#pragma unroll
        for (int half = 0; half < 2; ++half) {
            const int b = tid + half * 128;
            const int kb = keys_length[b];
            int rank = 0;
            for (int j = 0; j < B; ++j) {
                const int kj = keys_length[j];
                rank += (kj > kb) || (kj == kb && j < b);
            }
            g_perm[rank] = b;
        }
        if (tid < T) {
            int cnt = 0;
            for (int j = 0; j < B; ++j) cnt += (tid < keys_length[j]) ? 1 : 0;
            g_nvinv[tid] = cnt ? 1.f / (float)cnt : 0.f;
        }
    }
}

// ---------------- precompute A[B,T,6,H] (only t < kl) ----------------
__global__ void __launch_bounds__(128) pre_kernel(
    const float* __restrict__ inputs, const float* __restrict__ Wx,
    const float* __restrict__ Wts, const float* __restrict__ bg,
    const int* __restrict__ keys_length)
{
    const int b = blockIdx.x, k = threadIdx.x;
    const int kl = keys_length[b];
    if (kl == 0) return;
    __shared__ float xsT[IPT][66];
    __shared__ float Tts[T], Dts[T];
    const int tmax = kl;
    for (int idx = k; idx < tmax * IPT; idx += 128) {
        const int t = idx >> 7, i = idx & 127;
        xsT[i][t] = inputs[(long long)(b * T + t) * ROWLEN + 2 + i];
    }
    if (k < tmax) {
        Tts[k] = inputs[(long long)(b * T + k) * ROWLEN + 0];
        Dts[k] = inputs[(long long)(b * T + k) * ROWLEN + 1];
    }
    __syncthreads();

    const float wt0 = Wts[0 * H + k], wt1 = Wts[1 * H + k];
    const float wt2 = Wts[2 * H + k], wt3 = Wts[3 * H + k];
    const float wt4 = Wts[4 * H + k], wt5 = Wts[5 * H + k];
    float bgv[8];
#pragma unroll
    for (int g = 0; g < 8; ++g) bgv[g] = bg[g * H + k];

    float* Ab = g_A + ((long long)b * T * 6) * H + k;

    for (int t0 = 0; t0 < tmax; t0 += 16) {
        const int nt = min(16, tmax - t0);
        float T1v[16], T2v[16];
#pragma unroll
        for (int g = 0; g < 8; ++g) {
            u64 acc[8];
#pragma unroll
            for (int j = 0; j < 8; ++j) acc[j] = 0ull;
            const float* Wg = Wx + (long long)g * IPT * H + k;
#pragma unroll 4
            for (int i = 0; i < IPT; ++i) {
                const u64 wd = dup2(Wg[(long long)i * H]);
#pragma unroll
                for (int j = 0; j < 8; ++j)
                    fma2(acc[j], *(const u64*)&xsT[i][t0 + 2 * j], wd);
            }
#pragma unroll
            for (int j = 0; j < 8; ++j) {
                float v0, v1; un2(acc[j], v0, v1);
#pragma unroll
                for (int half = 0; half < 2; ++half) {
                    const int tt = 2 * j + half;
                    if (tt >= nt) continue;
                    const int t = t0 + tt;
                    const float v = half ? v1 : v0;
                    float* At = Ab + (long long)t * 6 * H;
                    if (g == 0)      At[0]     = v + bgv[0];
                    else if (g == 1) At[H]     = v + bgv[1];
                    else if (g == 2) At[2 * H] = v + bgv[2];
                    else if (g == 3) At[3 * H] = v + Tts[t] * wt4 + Dts[t] * wt5 + bgv[3];
                    else if (g == 4) T1v[tt] = sigf(v + sigf(Tts[t] * wt0) + bgv[4]);
                    else if (g == 5) T2v[tt] = sigf(v + sigf(Tts[t] * wt1) + bgv[5]);
                    else if (g == 6) At[4 * H] = T1v[tt] * sigf(v + sigf(Dts[t] * wt2) + bgv[6]);
                    else             At[5 * H] = T2v[tt] * sigf(v + sigf(Dts[t] * wt3) + bgv[7]);
                }
            }
        }
    }
}

// ---------------- qp = x_q @ Wc + bc (only 1 <= t < kl) ----------------
__global__ void __launch_bounds__(128) qp_kernel(
    const float* __restrict__ x_q, const int* __restrict__ keys_length)
{
    const int bt = blockIdx.x, k = threadIdx.x;
    const int b = bt >> 6, t = bt & 63;
    if (t == 0 || t >= keys_length[b]) return;
    __shared__ float xqT[Q][12];
    const float* xp = x_q + (long long)bt * S * Q;
    for (int idx = k; idx < S * Q; idx += 128) {
        const int s = idx >> 7, q = idx & 127;
        xqT[q][s] = xp[idx];
    }
    __syncthreads();
    const float bcv = g_bc[k];
    u64 acc[5];
#pragma unroll
    for (int p = 0; p < 5; ++p) acc[p] = dup2(bcv);
#pragma unroll 4
    for (int i = 0; i < Q; ++i) {
        const u64 wd = dup2(g_Wc[i * H + k]);
#pragma unroll
        for (int p = 0; p < 5; ++p)
            fma2(acc[p], *(const u64*)&xqT[i][2 * p], wd);
    }
    float* o = g_qp + (long long)bt * S * H + k;
#pragma unroll
    for (int p = 0; p < 5; ++p) {
        float v0, v1; un2(acc[p], v0, v1);
        o[(2 * p) * H] = v0; o[(2 * p + 1) * H] = v1;
    }
}

// ---------------- recurrent kernel: loss-free cell ----------------
__global__ void __launch_bounds__(256, 1) rec_kernel(
    const float* __restrict__ Wattn, const float* __restrict__ battn,
    const int* __restrict__ keys_length, float* __restrict__ out)
{
    extern __shared__ float sm[];
    const int tid = threadIdx.x;
    const int k = tid & 127, half = tid >> 7;
    const int lane = tid & 31, warp = tid >> 5;
    const int b = g_perm[blockIdx.x];
    const int kl = keys_length[b];

    // preload W1,W2,W3 into smem (contiguous in Wattn after Wattn0)
    {
        const float4* src = (const float4*)(Wattn + HH);
        float4* dst = (float4*)(sm + SM_W1);
        for (int i = tid; i < 3 * HH / 4; i += 256) dst[i] = src[i];
    }
    for (int i = tid; i < 2 * H * 12; i += 256) sm[SM_HT + i] = 0.f;
    __syncthreads();

    float* hT   = sm + SM_HT;
    float* bufT = sm + SM_BUF;

    const float b1v = battn[1 * H + k];
    const float b2v = battn[2 * H + k];
    const float b3v = battn[3 * H + k];

    float c[S];
#pragma unroll
    for (int s = 0; s < S; ++s) c[s] = 0.f;

    int t = 0;
    for (; t < kl; ++t) {
        // ---- phase A: prefetch cell inputs (half0) + load qp ----
        float a0 = 0.f, a1 = 0.f, a2 = 0.f, a3 = 0.f, td1 = 0.f, td2 = 0.f;
        if (half == 0) {
            const float* Ab = g_A + ((long long)((b * T + t) * 6)) * H + k;
            a0 = Ab[0]; a1 = Ab[H]; a2 = Ab[2 * H]; a3 = Ab[3 * H];
            td1 = Ab[4 * H]; td2 = Ab[5 * H];
        }
        if (t > 0) {
            const float* qpp = g_qp + ((long long)(b * T + t) * S) * H;
#pragma unroll
            for (int j = 0; j < 5; ++j) {
                const int s = half * 5 + j;
                sm[SM_QPS + s * H + k] = qpp[s * H + k];
            }
        }
        __syncthreads();

        if (t > 0) {
            // ---- phase B: scores + exp at store (uniform trip count!) ----
            const int group = tid >> 3, gl = tid & 7;
            const int iters = (t + 31) >> 5;     // same for all threads
#pragma unroll 1
            for (int s = 0; s < S; ++s) {
                const float4* qr = (const float4*)(sm + SM_QPS + s * H) + gl * 4;
                for (int i = 0; i < iters; ++i) {
                    const int tp = group + 32 * i;
                    const bool valid = tp < t;
                    float acc = 0.f;
                    if (valid) {
                        const float4* pkr = (const float4*)(g_pk + ((long long)((b * T + tp) * S + s)) * H) + gl * 4;
#pragma unroll
                        for (int j = 0; j < 4; ++j) {
                            const float4 q = qr[j], p = pkr[j];
                            acc += q.x * p.x + q.y * p.y + q.z * p.z + q.w * p.w;
                        }
                    }
                    acc += __shfl_xor_sync(0xffffffffu, acc, 1);
                    acc += __shfl_xor_sync(0xffffffffu, acc, 2);
                    acc += __shfl_xor_sync(0xffffffffu, acc, 4);
                    if (valid && gl == 0) sm[SM_SSM + s * T + tp] = __expf(acc);
                }
            }
            __syncthreads();

            // ---- phase C: normalize (sum + scale) per s over 8 warps ----
            for (int s = warp; s < S; s += 8) {
                float* row = sm + SM_SSM + s * T;
                float sum = 0.f;
                for (int tp = lane; tp < t; tp += 32) sum += row[tp];
#pragma unroll
                for (int o = 16; o > 0; o >>= 1) sum += __shfl_xor_sync(0xffffffffu, sum, o);
                const float inv = __fdividef(1.f, sum);
                for (int tp = lane; tp < t; tp += 32) row[tp] *= inv;
            }
            __syncthreads();

            // ---- phase D: ctx, s-split 4/6 ----
            if (half == 0) {
                float cx[4] = {0.f, 0.f, 0.f, 0.f};
                const float* pvb = g_pv + ((long long)b * T * S) * H + k;
#pragma unroll 4
                for (int tp = 0; tp < t; ++tp) {
                    const float* pvr = pvb + (long long)tp * S * H;
#pragma unroll
                    for (int s = 0; s < 4; ++s) cx[s] += sm[SM_SSM + s * T + tp] * pvr[s * H];
                }
#pragma unroll
                for (int s = 0; s < 4; ++s) bufT[k * 12 + s] = cx[s];
            } else {
                float cx[6] = {0.f, 0.f, 0.f, 0.f, 0.f, 0.f};
                const float* pvb = g_pv + ((long long)b * T * S) * H + k + 4 * H;
#pragma unroll 4
                for (int tp = 0; tp < t; ++tp) {
                    const float* pvr = pvb + (long long)tp * S * H;
#pragma unroll
                    for (int s = 0; s < 6; ++s) cx[s] += sm[SM_SSM + (s + 4) * T + tp] * pvr[s * H];
                }
#pragma unroll
                for (int s = 0; s < 6; ++s) bufT[k * 12 + 4 + s] = cx[s];
            }
            __syncthreads();
        }

        // ---- phase E: combined gate + at GEMMs ----
        u64 A0[5], A1[5], At2[2];     // half0
        if (half == 0) {
#pragma unroll
            for (int p = 0; p < 5; ++p) { A0[p] = 0ull; A1[p] = 0ull; }
            At2[0] = dup2(b3v); At2[1] = dup2(b3v);
            const float2* Wp = g_Wh01 + k;
#pragma unroll 4
            for (int h = 0; h < H; ++h) {
                const float2 w01 = Wp[h * H];
                const u64 w0 = dup2(w01.x);
                const u64 w1 = dup2(w01.y);
                const u64 w3 = dup2(sm[SM_W3 + h * H + k]);
                const float* hr = hT + h * 12;
                const float* br = bufT + h * 12;
#pragma unroll
                for (int p = 0; p < 5; ++p) {
                    const u64 hp = *(const u64*)(hr + 2 * p);
                    fma2(A0[p], hp, w0); fma2(A1[p], hp, w1);
                }
                fma2(At2[0], *(const u64*)(br),     w3);
                fma2(At2[1], *(const u64*)(br + 2), w3);
            }
        } else {
            u64 A2[5], A3[5], At3[3];
#pragma unroll
            for (int p = 0; p < 5; ++p) { A2[p] = 0ull; A3[p] = 0ull; }
#pragma unroll
            for (int j = 0; j < 3; ++j) At3[j] = dup2(b3v);
            const float2* Wp = g_Wh23 + k;
#pragma unroll 4
            for (int h = 0; h < H; ++h) {
                const float2 w23 = Wp[h * H];
                const u64 w2  = dup2(w23.x);
                const u64 w3g = dup2(w23.y);
                const u64 w3a = dup2(sm[SM_W3 + h * H + k]);
                const float* hr = hT + h * 12;
                const float* br = bufT + h * 12;
#pragma unroll
                for (int p = 0; p < 5; ++p) {
                    const u64 hp = *(const u64*)(hr + 2 * p);
                    fma2(A2[p], hp, w2); fma2(A3[p], hp, w3g);
                }
#pragma unroll
                for (int j = 0; j < 3; ++j)
                    fma2(At3[j], *(const u64*)(br + 4 + 2 * j), w3a);
            }
#pragma unroll
            for (int p = 0; p < 5; ++p) {
                float v0, v1;
                un2(A2[p], v0, v1);
                sm[SM_ST2 + (2 * p) * H + k] = v0; sm[SM_ST2 + (2 * p + 1) * H + k] = v1;
                un2(A3[p], v0, v1);
                sm[SM_ST3 + (2 * p) * H + k] = v0; sm[SM_ST3 + (2 * p + 1) * H + k] = v1;
            }
#pragma unroll
            for (int j = 0; j < 3; ++j) {
                float v0, v1; un2(At3[j], v0, v1);
                sm[SM_ATS + (2 * j) * H + k] = v0; sm[SM_ATS + (2 * j + 1) * H + k] = v1;
            }
        }
        __syncthreads();

        // ---- phase F: cell (half0 only, loss-free) ----
        if (half == 0) {
            float G0[S], G1[S], at0[4];
#pragma unroll
            for (int p = 0; p < 5; ++p) {
                un2(A0[p], G0[2 * p], G0[2 * p + 1]);
                un2(A1[p], G1[2 * p], G1[2 * p + 1]);
            }
            un2(At2[0], at0[0], at0[1]);
            un2(At2[1], at0[2], at0[3]);
#pragma unroll
            for (int s = 0; s < S; ++s) {
                const float g2 = sm[SM_ST2 + s * H + k];
                const float g3 = sm[SM_ST3 + s * H + k];
                float atv = 1.f;
                if (t > 0) atv = (s < 4) ? at0[s] : sm[SM_ATS + (s - 4) * H + k];
                const float it = sigf(a0 + G0[s]);
                const float ft = sigf(a1 + G1[s]);
                const float ct = tanhfast(a2 + g2);
                const float ot = sigf(a3 + g3);
                const float itp = it * atv, ftp = ft * atv;
                const float fc = ftp * c[s];
                const float ic = itp * ct;
                const float chat = fc + ic * td1;
                c[s] = fc + ic * td2;
                hT[k * 12 + s] = ot * tanhfast(chat);
            }
        }
        __syncthreads();

        // ---- phase G: pk / pv GEMMs + output ----
        if (half == 0) {
            u64 P[5];
#pragma unroll
            for (int p = 0; p < 5; ++p) P[p] = dup2(b1v);
#pragma unroll 4
            for (int h = 0; h < H; ++h) {
                const u64 w = dup2(sm[SM_W1 + h * H + k]);
                const float* hr = hT + h * 12;
#pragma unroll
                for (int p = 0; p < 5; ++p)
                    fma2(P[p], *(const u64*)(hr + 2 * p), w);
            }
            float* pkp = g_pk + ((long long)((b * T + t) * S)) * H + k;
#pragma unroll
            for (int p = 0; p < 5; ++p) {
                float v0, v1; un2(P[p], v0, v1);
                pkp[(2 * p) * H] = v0; pkp[(2 * p + 1) * H] = v1;
            }
        } else {
            u64 P[5];
#pragma unroll
            for (int p = 0; p < 5; ++p) P[p] = dup2(b2v);
#pragma unroll 4
            for (int h = 0; h < H; ++h) {
                const u64 w = dup2(sm[SM_W2 + h * H + k]);
                const float* hr = hT + h * 12;
#pragma unroll
                for (int p = 0; p < 5; ++p)
                    fma2(P[p], *(const u64*)(hr + 2 * p), w);
            }
            float* pvp = g_pv + ((long long)((b * T + t) * S)) * H + k;
#pragma unroll
            for (int p = 0; p < 5; ++p) {
                float v0, v1; un2(P[p], v0, v1);
                pvp[(2 * p) * H] = v0; pvp[(2 * p + 1) * H] = v1;
            }
            float* outp = out + ((long long)((b * T + t) * S)) * H + k;
#pragma unroll
            for (int s = 0; s < S; ++s) outp[s * H] = hT[k * 12 + s];
        }
        __syncthreads();
    }

    // masked steps: zeros
    for (; t < T; ++t) {
        float* outp = out + ((long long)((b * T + t) * S)) * H + k;
#pragma unroll
        for (int j = 0; j < 5; ++j) outp[(half * 5 + j) * H] = 0.f;
    }

    // final h, c
    if (half == 0) {
        float* oh = out + HSEQ_ELEMS + ((long long)b * S) * H + k;
#pragma unroll
        for (int s = 0; s < S; ++s) oh[s * H] = hT[k * 12 + s];
        float* oc = oh + HC_ELEMS;
#pragma unroll
        for (int s = 0; s < S; ++s) oc[s * H] = c[s];
    }
}

// ---------------- bce: loss from hseq (parallel post-pass) ----------------
__global__ void __launch_bounds__(128) bce_kernel(
    const float* __restrict__ out, const float* __restrict__ austgn_y,
    const int* __restrict__ keys_length)
{
    const int bt = blockIdx.x;
    const int b = bt >> 6, t = bt & 63;
    const int k = threadIdx.x;
    __shared__ float red[4];
    if (t >= keys_length[b]) {
        if (k == 0) g_lpart[bt] = 0.f;
        return;
    }
    const float y = austgn_y[bt];
    const float* hp = out + ((long long)bt * S) * H + k;
    float bsum = 0.f;
#pragma unroll
    for (int s = 0; s < S; ++s) {
        const float hn = hp[s * H];
        const float p = fminf(fmaxf(hn, 1e-7f), 1.f - 1e-7f);
        bsum += -(y * __logf(p) + (1.f - y) * __logf(1.f - p));
    }
#pragma unroll
    for (int o = 16; o > 0; o >>= 1) bsum += __shfl_xor_sync(0xffffffffu, bsum, o);
    if ((k & 31) == 0) red[k >> 5] = bsum;
    __syncthreads();
    if (k == 0)
        g_lpart[bt] = (red[0] + red[1] + red[2] + red[3]) * g_nvinv[t] * (1.f / (float)(S * H));
}

// ---------------- final deterministic loss reduction ----------------
__global__ void __launch_bounds__(256) loss_kernel(float* __restrict__ out)
{
    __shared__ float smr[256];
    const int i = threadIdx.x;
    float sum = 0.f;
    for (int j = 0; j < 64; ++j) sum += g_lpart[i * 64 + j];
    smr[i] = sum;
    __syncthreads();
    for (int off = 128; off > 0; off >>= 1) {
        if (i < off) smr[i] += smr[i + off];
        __syncthreads();
    }
    if (i == 0) out[HSEQ_ELEMS + 2 * HC_ELEMS] = smr[0];
}

// ---------------- launch ----------------
extern "C" void kernel_launch(void* const* d_in, const int* in_sizes, int n_in,
                              void* d_out, int out_size)
{
    (void)in_sizes; (void)n_in; (void)out_size;
    const float* inputs      = (const float*)d_in[0];
    const float* x_q         = (const float*)d_in[1];
    const float* austgn_y    = (const float*)d_in[2];
    const int*   keys_length = (const int*)  d_in[3];
    const float* Wx          = (const float*)d_in[4];
    const float* Wh          = (const float*)d_in[5];
    const float* Wts         = (const float*)d_in[6];
    const float* bg          = (const float*)d_in[7];
    const float* Wa          = (const float*)d_in[8];
    const float* ba          = (const float*)d_in[9];
    const float* Wattn       = (const float*)d_in[10];
    const float* battn       = (const float*)d_in[11];
    float* out = (float*)d_out;

    static int smem_set = 0;
    if (!smem_set) {
        cudaFuncSetAttribute(rec_kernel, cudaFuncAttributeMaxDynamicSharedMemorySize,
                             SM_TOTAL * (int)sizeof(float));
        smem_set = 1;
    }

    fold_kernel<<<256, 128>>>(Wa, ba, Wattn, battn, Wh, keys_length);
    pre_kernel<<<B, 128>>>(inputs, Wx, Wts, bg, keys_length);
    qp_kernel<<<B * T, 128>>>(x_q, keys_length);
    rec_kernel<<<B, 256, SM_TOTAL * (int)sizeof(float)>>>(
        Wattn, battn, keys_length, out);
    bce_kernel<<<B * T, 128>>>(out, austgn_y, keys_length);
    loss_kernel<<<1, 256>>>(out);
}

// round 10
// speedup vs baseline: 1.2359x; 1.0875x over previous
#include <cuda_runtime.h>
#include <math.h>

namespace {
constexpr int B = 256, T = 64, S = 10, H = 128, IPT = 128, Q = 128;
constexpr int ROWLEN = 2 + IPT;
constexpr int HH = H * H;
constexpr long long HSEQ_ELEMS = (long long)B * T * S * H;
constexpr long long HC_ELEMS   = (long long)B * S * H;
// dynamic smem layout (float offsets) — weights resident
constexpr int SM_W1  = 0;
constexpr int SM_W2  = SM_W1 + HH;
constexpr int SM_W3  = SM_W2 + HH;
constexpr int SM_HT  = SM_W3 + HH;          // [128][12]
constexpr int SM_BUF = SM_HT + H * 12;      // [128][12]
constexpr int SM_QPS = SM_BUF + H * 12;     // [10][128]
constexpr int SM_SSM = SM_QPS + S * H;      // [10][64]
constexpr int SM_ST2 = SM_SSM + S * T;      // [10][128]
constexpr int SM_ST3 = SM_ST2 + S * H;      // [10][128]
constexpr int SM_ATS = SM_ST3 + S * H;      // [6][128]
constexpr int SM_TOTAL = SM_ATS + 6 * H;    // 57472 floats = 229888 B
}

// ---------------- scratch ----------------
__device__ float g_qp[B * T * S * H];
__device__ float g_A [B * T * 6 * H];
__device__ float g_pk[B * T * S * H];
__device__ float g_pv[B * T * S * H];
__device__ float g_Wc[H * H];
__device__ float g_bc[H];
__device__ float2 g_Wh01[H * H];        // interleaved gates 0,1
__device__ float2 g_Wh23[H * H];        // interleaved gates 2,3
__device__ float g_nvinv[T];
__device__ float g_lpart[B * T];        // per-(b,t) loss partials
__device__ int   g_perm[B];

// ---------------- f32x2 helpers ----------------
using u64 = unsigned long long;
__device__ __forceinline__ u64 pk2(float lo, float hi) {
    u64 r; asm("mov.b64 %0,{%1,%2};" : "=l"(r) : "f"(lo), "f"(hi)); return r;
}
__device__ __forceinline__ u64 dup2(float x) { return pk2(x, x); }
__device__ __forceinline__ void un2(u64 v, float& a, float& b) {
    asm("mov.b64 {%0,%1},%2;" : "=f"(a), "=f"(b) : "l"(v));
}
__device__ __forceinline__ void fma2(u64& d, u64 a, u64 b) {
    asm("fma.rn.f32x2 %0,%1,%2,%0;" : "+l"(d) : "l"(a), "l"(b));
}

__device__ __forceinline__ float sigf(float x) {
    return __fdividef(1.f, 1.f + __expf(-x));
}
__device__ __forceinline__ float tanhfast(float x) {
    return __fdividef(2.f, 1.f + __expf(-2.f * x)) - 1.f;
}

// ---------------- fold: q-weights + Wh interleave + perm/nvinv ----------------
__global__ void __launch_bounds__(128) fold_kernel(
    const float* __restrict__ Wa, const float* __restrict__ ba,
    const float* __restrict__ Wattn, const float* __restrict__ battn,
    const float* __restrict__ Wh, const int* __restrict__ keys_length)
{
    const int bx = blockIdx.x, tid = threadIdx.x;
    if (bx < 128) {
        const int q = bx, h = tid;
        const float scale = 0.08838834764831845f;
        float acc = 0.f;
        for (int j = 0; j < H; ++j) acc += Wa[q * H + j] * Wattn[j * H + h];
        g_Wc[q * H + h] = acc * scale;
        if (q == 0) {
            float bacc = battn[h];
            for (int j = 0; j < H; ++j) bacc += ba[j] * Wattn[j * H + h];
            g_bc[h] = bacc * scale;
        }
        return;
    }
    const int e = (bx - 128) * 128 + tid;
    g_Wh01[e] = make_float2(Wh[e], Wh[HH + e]);
    g_Wh23[e] = make_float2(Wh[2 * HH + e], Wh[3 * HH + e]);

    if (bx == 128) {
#pragma unroll
        for (int half = 0; half < 2; ++half) {
            const int b = tid + half * 128;
            const int kb = keys_length[b];
            int rank = 0;
            for (int j = 0; j < B; ++j) {
                const int kj = keys_length[j];
                rank += (kj > kb) || (kj == kb && j < b);
            }
            g_perm[rank] = b;
        }
        if (tid < T) {
            int cnt = 0;
            for (int j = 0; j < B; ++j) cnt += (tid < keys_length[j]) ? 1 : 0;
            g_nvinv[tid] = cnt ? 1.f / (float)cnt : 0.f;
        }
    }
}

// ---------------- precompute A[B,T,6,H] (only t < kl) ----------------
__global__ void __launch_bounds__(128) pre_kernel(
    const float* __restrict__ inputs, const float* __restrict__ Wx,
    const float* __restrict__ Wts, const float* __restrict__ bg,
    const int* __restrict__ keys_length)
{
    const int b = blockIdx.x, k = threadIdx.x;
    const int kl = keys_length[b];
    if (kl == 0) return;
    __shared__ float xsT[IPT][66];
    __shared__ float Tts[T], Dts[T];
    const int tmax = kl;
    for (int idx = k; idx < tmax * IPT; idx += 128) {
        const int t = idx >> 7, i = idx & 127;
        xsT[i][t] = inputs[(long long)(b * T + t) * ROWLEN + 2 + i];
    }
    if (k < tmax) {
        Tts[k] = inputs[(long long)(b * T + k) * ROWLEN + 0];
        Dts[k] = inputs[(long long)(b * T + k) * ROWLEN + 1];
    }
    __syncthreads();

    const float wt0 = Wts[0 * H + k], wt1 = Wts[1 * H + k];
    const float wt2 = Wts[2 * H + k], wt3 = Wts[3 * H + k];
    const float wt4 = Wts[4 * H + k], wt5 = Wts[5 * H + k];
    float bgv[8];
#pragma unroll
    for (int g = 0; g < 8; ++g) bgv[g] = bg[g * H + k];

    float* Ab = g_A + ((long long)b * T * 6) * H + k;

    for (int t0 = 0; t0 < tmax; t0 += 16) {
        const int nt = min(16, tmax - t0);
        float T1v[16], T2v[16];
#pragma unroll
        for (int g = 0; g < 8; ++g) {
            u64 acc[8];
#pragma unroll
            for (int j = 0; j < 8; ++j) acc[j] = 0ull;
            const float* Wg = Wx + (long long)g * IPT * H + k;
#pragma unroll 4
            for (int i = 0; i < IPT; ++i) {
                const u64 wd = dup2(Wg[(long long)i * H]);
#pragma unroll
                for (int j = 0; j < 8; ++j)
                    fma2(acc[j], *(const u64*)&xsT[i][t0 + 2 * j], wd);
            }
#pragma unroll
            for (int j = 0; j < 8; ++j) {
                float v0, v1; un2(acc[j], v0, v1);
#pragma unroll
                for (int half = 0; half < 2; ++half) {
                    const int tt = 2 * j + half;
                    if (tt >= nt) continue;
                    const int t = t0 + tt;
                    const float v = half ? v1 : v0;
                    float* At = Ab + (long long)t * 6 * H;
                    if (g == 0)      At[0]     = v + bgv[0];
                    else if (g == 1) At[H]     = v + bgv[1];
                    else if (g == 2) At[2 * H] = v + bgv[2];
                    else if (g == 3) At[3 * H] = v + Tts[t] * wt4 + Dts[t] * wt5 + bgv[3];
                    else if (g == 4) T1v[tt] = sigf(v + sigf(Tts[t] * wt0) + bgv[4]);
                    else if (g == 5) T2v[tt] = sigf(v + sigf(Tts[t] * wt1) + bgv[5]);
                    else if (g == 6) At[4 * H] = T1v[tt] * sigf(v + sigf(Dts[t] * wt2) + bgv[6]);
                    else             At[5 * H] = T2v[tt] * sigf(v + sigf(Dts[t] * wt3) + bgv[7]);
                }
            }
        }
    }
}

// ---------------- qp = x_q @ Wc + bc (only 1 <= t < kl) ----------------
__global__ void __launch_bounds__(128) qp_kernel(
    const float* __restrict__ x_q, const int* __restrict__ keys_length)
{
    const int bt = blockIdx.x, k = threadIdx.x;
    const int b = bt >> 6, t = bt & 63;
    if (t == 0 || t >= keys_length[b]) return;
    __shared__ float xqT[Q][12];
    const float* xp = x_q + (long long)bt * S * Q;
    for (int idx = k; idx < S * Q; idx += 128) {
        const int s = idx >> 7, q = idx & 127;
        xqT[q][s] = xp[idx];
    }
    __syncthreads();
    const float bcv = g_bc[k];
    u64 acc[5];
#pragma unroll
    for (int p = 0; p < 5; ++p) acc[p] = dup2(bcv);
#pragma unroll 4
    for (int i = 0; i < Q; ++i) {
        const u64 wd = dup2(g_Wc[i * H + k]);
#pragma unroll
        for (int p = 0; p < 5; ++p)
            fma2(acc[p], *(const u64*)&xqT[i][2 * p], wd);
    }
    float* o = g_qp + (long long)bt * S * H + k;
#pragma unroll
    for (int p = 0; p < 5; ++p) {
        float v0, v1; un2(acc[p], v0, v1);
        o[(2 * p) * H] = v0; o[(2 * p + 1) * H] = v1;
    }
}

// ---------------- recurrent kernel ----------------
__global__ void __launch_bounds__(256, 1) rec_kernel(
    const float* __restrict__ Wattn, const float* __restrict__ battn,
    const int* __restrict__ keys_length, float* __restrict__ out)
{
    extern __shared__ float sm[];
    const int tid = threadIdx.x;
    const int k = tid & 127, half = tid >> 7;
    const int lane = tid & 31, warp = tid >> 5;
    const int b = g_perm[blockIdx.x];
    const int kl = keys_length[b];

    // preload W1,W2,W3 into smem (contiguous in Wattn after Wattn0)
    {
        const float4* src = (const float4*)(Wattn + HH);
        float4* dst = (float4*)(sm + SM_W1);
        for (int i = tid; i < 3 * HH / 4; i += 256) dst[i] = src[i];
    }
    for (int i = tid; i < 2 * H * 12; i += 256) sm[SM_HT + i] = 0.f;
    __syncthreads();

    float* hT   = sm + SM_HT;
    float* bufT = sm + SM_BUF;

    const float b1v = battn[1 * H + k];
    const float b2v = battn[2 * H + k];
    const float b3v = battn[3 * H + k];

    float c[S];
#pragma unroll
    for (int s = 0; s < S; ++s) c[s] = 0.f;

    int t = 0;
    for (; t < kl; ++t) {
        // ---- phase A: prefetch cell inputs (half0) + load qp ----
        float a0 = 0.f, a1 = 0.f, a2 = 0.f, a3 = 0.f, td1 = 0.f, td2 = 0.f;
        if (half == 0) {
            const float* Ab = g_A + ((long long)((b * T + t) * 6)) * H + k;
            a0 = Ab[0]; a1 = Ab[H]; a2 = Ab[2 * H]; a3 = Ab[3 * H];
            td1 = Ab[4 * H]; td2 = Ab[5 * H];
        }
        if (t > 0) {
            const float* qpp = g_qp + ((long long)(b * T + t) * S) * H;
#pragma unroll
            for (int j = 0; j < 5; ++j) {
                const int s = half * 5 + j;
                sm[SM_QPS + s * H + k] = qpp[s * H + k];
            }
        }
        __syncthreads();

        if (t > 0) {
            // ---- phase B: flat-index scores + exp at store ----
            // s,tp from idx via float reciprocal (no IDIV); uniform trips.
            const int group = tid >> 3, gl = tid & 7;
            const int nd = S * t;
            const int iters = (nd + 31) >> 5;
            const float tinv = __fdividef(1.f, (float)t);
            for (int i = 0; i < iters; ++i) {
                const int idx = group + 32 * i;
                const bool valid = idx < nd;
                int s = 0, tp = 0;
                float acc = 0.f;
                if (valid) {
                    s = (int)(((float)idx + 0.5f) * tinv);
                    tp = idx - s * t;
                    const float4* pkr = (const float4*)(g_pk + ((long long)((b * T + tp) * S + s)) * H) + gl * 4;
                    const float4* qr  = (const float4*)(sm + SM_QPS + s * H) + gl * 4;
#pragma unroll
                    for (int j = 0; j < 4; ++j) {
                        const float4 q = qr[j], p = pkr[j];
                        acc += q.x * p.x + q.y * p.y + q.z * p.z + q.w * p.w;
                    }
                }
                acc += __shfl_xor_sync(0xffffffffu, acc, 1);
                acc += __shfl_xor_sync(0xffffffffu, acc, 2);
                acc += __shfl_xor_sync(0xffffffffu, acc, 4);
                if (valid && gl == 0) sm[SM_SSM + s * T + tp] = __expf(acc);
            }
            __syncthreads();

            // ---- phase C: normalize (sum + scale) per s over 8 warps ----
            for (int s = warp; s < S; s += 8) {
                float* row = sm + SM_SSM + s * T;
                float sum = 0.f;
                for (int tp = lane; tp < t; tp += 32) sum += row[tp];
#pragma unroll
                for (int o = 16; o > 0; o >>= 1) sum += __shfl_xor_sync(0xffffffffu, sum, o);
                const float inv = __fdividef(1.f, sum);
                for (int tp = lane; tp < t; tp += 32) row[tp] *= inv;
            }
            __syncthreads();

            // ---- phase D: ctx, s-split 4/6, deep unroll for MLP ----
            if (half == 0) {
                float cx[4] = {0.f, 0.f, 0.f, 0.f};
                const float* pvb = g_pv + ((long long)b * T * S) * H + k;
#pragma unroll 8
                for (int tp = 0; tp < t; ++tp) {
                    const float* pvr = pvb + (long long)tp * S * H;
#pragma unroll
                    for (int s = 0; s < 4; ++s) cx[s] += sm[SM_SSM + s * T + tp] * pvr[s * H];
                }
#pragma unroll
                for (int s = 0; s < 4; ++s) bufT[k * 12 + s] = cx[s];
            } else {
                float cx[6] = {0.f, 0.f, 0.f, 0.f, 0.f, 0.f};
                const float* pvb = g_pv + ((long long)b * T * S) * H + k + 4 * H;
#pragma unroll 8
                for (int tp = 0; tp < t; ++tp) {
                    const float* pvr = pvb + (long long)tp * S * H;
#pragma unroll
                    for (int s = 0; s < 6; ++s) cx[s] += sm[SM_SSM + (s + 4) * T + tp] * pvr[s * H];
                }
#pragma unroll
                for (int s = 0; s < 6; ++s) bufT[k * 12 + 4 + s] = cx[s];
            }
            __syncthreads();
        }

        // ---- phase E: combined gate + at GEMMs ----
        u64 A0[5], A1[5], At2[2];     // half0
        if (half == 0) {
#pragma unroll
            for (int p = 0; p < 5; ++p) { A0[p] = 0ull; A1[p] = 0ull; }
            At2[0] = dup2(b3v); At2[1] = dup2(b3v);
            const float2* Wp = g_Wh01 + k;
#pragma unroll 8
            for (int h = 0; h < H; ++h) {
                const float2 w01 = Wp[h * H];
                const u64 w0 = dup2(w01.x);
                const u64 w1 = dup2(w01.y);
                const u64 w3 = dup2(sm[SM_W3 + h * H + k]);
                const float* hr = hT + h * 12;
                const float* br = bufT + h * 12;
#pragma unroll
                for (int p = 0; p < 5; ++p) {
                    const u64 hp = *(const u64*)(hr + 2 * p);
                    fma2(A0[p], hp, w0); fma2(A1[p], hp, w1);
                }
                fma2(At2[0], *(const u64*)(br),     w3);
                fma2(At2[1], *(const u64*)(br + 2), w3);
            }
        } else {
            u64 A2[5], A3[5], At3[3];
#pragma unroll
            for (int p = 0; p < 5; ++p) { A2[p] = 0ull; A3[p] = 0ull; }
#pragma unroll
            for (int j = 0; j < 3; ++j) At3[j] = dup2(b3v);
            const float2* Wp = g_Wh23 + k;
#pragma unroll 8
            for (int h = 0; h < H; ++h) {
                const float2 w23 = Wp[h * H];
                const u64 w2  = dup2(w23.x);
                const u64 w3g = dup2(w23.y);
                const u64 w3a = dup2(sm[SM_W3 + h * H + k]);
                const float* hr = hT + h * 12;
                const float* br = bufT + h * 12;
#pragma unroll
                for (int p = 0; p < 5; ++p) {
                    const u64 hp = *(const u64*)(hr + 2 * p);
                    fma2(A2[p], hp, w2); fma2(A3[p], hp, w3g);
                }
#pragma unroll
                for (int j = 0; j < 3; ++j)
                    fma2(At3[j], *(const u64*)(br + 4 + 2 * j), w3a);
            }
#pragma unroll
            for (int p = 0; p < 5; ++p) {
                float v0, v1;
                un2(A2[p], v0, v1);
                sm[SM_ST2 + (2 * p) * H + k] = v0; sm[SM_ST2 + (2 * p + 1) * H + k] = v1;
                un2(A3[p], v0, v1);
                sm[SM_ST3 + (2 * p) * H + k] = v0; sm[SM_ST3 + (2 * p + 1) * H + k] = v1;
            }
#pragma unroll
            for (int j = 0; j < 3; ++j) {
                float v0, v1; un2(At3[j], v0, v1);
                sm[SM_ATS + (2 * j) * H + k] = v0; sm[SM_ATS + (2 * j + 1) * H + k] = v1;
            }
        }
        __syncthreads();

        // ---- phase F: cell (half0 only, loss-free) ----
        if (half == 0) {
            float G0[S], G1[S], at0[4];
#pragma unroll
            for (int p = 0; p < 5; ++p) {
                un2(A0[p], G0[2 * p], G0[2 * p + 1]);
                un2(A1[p], G1[2 * p], G1[2 * p + 1]);
            }
            un2(At2[0], at0[0], at0[1]);
            un2(At2[1], at0[2], at0[3]);
#pragma unroll
            for (int s = 0; s < S; ++s) {
                const float g2 = sm[SM_ST2 + s * H + k];
                const float g3 = sm[SM_ST3 + s * H + k];
                float atv = 1.f;
                if (t > 0) atv = (s < 4) ? at0[s] : sm[SM_ATS + (s - 4) * H + k];
                const float it = sigf(a0 + G0[s]);
                const float ft = sigf(a1 + G1[s]);
                const float ct = tanhfast(a2 + g2);
                const float ot = sigf(a3 + g3);
                const float itp = it * atv, ftp = ft * atv;
                const float fc = ftp * c[s];
                const float ic = itp * ct;
                const float chat = fc + ic * td1;
                c[s] = fc + ic * td2;
                hT[k * 12 + s] = ot * tanhfast(chat);
            }
        }
        __syncthreads();

        // ---- phase G: pk / pv GEMMs + output ----
        if (half == 0) {
            u64 P[5];
#pragma unroll
            for (int p = 0; p < 5; ++p) P[p] = dup2(b1v);
#pragma unroll 8
            for (int h = 0; h < H; ++h) {
                const u64 w = dup2(sm[SM_W1 + h * H + k]);
                const float* hr = hT + h * 12;
#pragma unroll
                for (int p = 0; p < 5; ++p)
                    fma2(P[p], *(const u64*)(hr + 2 * p), w);
            }
            float* pkp = g_pk + ((long long)((b * T + t) * S)) * H + k;
#pragma unroll
            for (int p = 0; p < 5; ++p) {
                float v0, v1; un2(P[p], v0, v1);
                pkp[(2 * p) * H] = v0; pkp[(2 * p + 1) * H] = v1;
            }
        } else {
            u64 P[5];
#pragma unroll
            for (int p = 0; p < 5; ++p) P[p] = dup2(b2v);
#pragma unroll 8
            for (int h = 0; h < H; ++h) {
                const u64 w = dup2(sm[SM_W2 + h * H + k]);
                const float* hr = hT + h * 12;
#pragma unroll
                for (int p = 0; p < 5; ++p)
                    fma2(P[p], *(const u64*)(hr + 2 * p), w);
            }
            float* pvp = g_pv + ((long long)((b * T + t) * S)) * H + k;
#pragma unroll
            for (int p = 0; p < 5; ++p) {
                float v0, v1; un2(P[p], v0, v1);
                pvp[(2 * p) * H] = v0; pvp[(2 * p + 1) * H] = v1;
            }
            float* outp = out + ((long long)((b * T + t) * S)) * H + k;
#pragma unroll
            for (int s = 0; s < S; ++s) outp[s * H] = hT[k * 12 + s];
        }
        __syncthreads();
    }

    // masked steps: zeros
    for (; t < T; ++t) {
        float* outp = out + ((long long)((b * T + t) * S)) * H + k;
#pragma unroll
        for (int j = 0; j < 5; ++j) outp[(half * 5 + j) * H] = 0.f;
    }

    // final h, c
    if (half == 0) {
        float* oh = out + HSEQ_ELEMS + ((long long)b * S) * H + k;
#pragma unroll
        for (int s = 0; s < S; ++s) oh[s * H] = hT[k * 12 + s];
        float* oc = oh + HC_ELEMS;
#pragma unroll
        for (int s = 0; s < S; ++s) oc[s * H] = c[s];
    }
}

// ---------------- bce: loss from hseq (parallel post-pass) ----------------
__global__ void __launch_bounds__(128) bce_kernel(
    const float* __restrict__ out, const float* __restrict__ austgn_y,
    const int* __restrict__ keys_length)
{
    const int bt = blockIdx.x;
    const int b = bt >> 6, t = bt & 63;
    const int k = threadIdx.x;
    __shared__ float red[4];
    if (t >= keys_length[b]) {
        if (k == 0) g_lpart[bt] = 0.f;
        return;
    }
    const float y = austgn_y[bt];
    const float* hp = out + ((long long)bt * S) * H + k;
    float bsum = 0.f;
#pragma unroll
    for (int s = 0; s < S; ++s) {
        const float hn = hp[s * H];
        const float p = fminf(fmaxf(hn, 1e-7f), 1.f - 1e-7f);
        bsum += -(y * __logf(p) + (1.f - y) * __logf(1.f - p));
    }
#pragma unroll
    for (int o = 16; o > 0; o >>= 1) bsum += __shfl_xor_sync(0xffffffffu, bsum, o);
    if ((k & 31) == 0) red[k >> 5] = bsum;
    __syncthreads();
    if (k == 0)
        g_lpart[bt] = (red[0] + red[1] + red[2] + red[3]) * g_nvinv[t] * (1.f / (float)(S * H));
}

// ---------------- final deterministic loss reduction ----------------
__global__ void __launch_bounds__(256) loss_kernel(float* __restrict__ out)
{
    __shared__ float smr[256];
    const int i = threadIdx.x;
    float sum = 0.f;
    for (int j = 0; j < 64; ++j) sum += g_lpart[i * 64 + j];
    smr[i] = sum;
    __syncthreads();
    for (int off = 128; off > 0; off >>= 1) {
        if (i < off) smr[i] += smr[i + off];
        __syncthreads();
    }
    if (i == 0) out[HSEQ_ELEMS + 2 * HC_ELEMS] = smr[0];
}

// ---------------- launch ----------------
extern "C" void kernel_launch(void* const* d_in, const int* in_sizes, int n_in,
                              void* d_out, int out_size)
{
    (void)in_sizes; (void)n_in; (void)out_size;
    const float* inputs      = (const float*)d_in[0];
    const float* x_q         = (const float*)d_in[1];
    const float* austgn_y    = (const float*)d_in[2];
    const int*   keys_length = (const int*)  d_in[3];
    const float* Wx          = (const float*)d_in[4];
    const float* Wh          = (const float*)d_in[5];
    const float* Wts         = (const float*)d_in[6];
    const float* bg          = (const float*)d_in[7];
    const float* Wa          = (const float*)d_in[8];
    const float* ba          = (const float*)d_in[9];
    const float* Wattn       = (const float*)d_in[10];
    const float* battn       = (const float*)d_in[11];
    float* out = (float*)d_out;

    static int smem_set = 0;
    if (!smem_set) {
        cudaFuncSetAttribute(rec_kernel, cudaFuncAttributeMaxDynamicSharedMemorySize,
                             SM_TOTAL * (int)sizeof(float));
        smem_set = 1;
    }

    fold_kernel<<<256, 128>>>(Wa, ba, Wattn, battn, Wh, keys_length);
    pre_kernel<<<B, 128>>>(inputs, Wx, Wts, bg, keys_length);
    qp_kernel<<<B * T, 128>>>(x_q, keys_length);
    rec_kernel<<<B, 256, SM_TOTAL * (int)sizeof(float)>>>(
        Wattn, battn, keys_length, out);
    bce_kernel<<<B * T, 128>>>(out, austgn_y, keys_length);
    loss_kernel<<<1, 256>>>(out);
}

// round 11
// speedup vs baseline: 1.2459x; 1.0081x over previous
#include <cuda_runtime.h>
#include <math.h>

namespace {
constexpr int B = 256, T = 64, S = 10, H = 128, IPT = 128, Q = 128;
constexpr int ROWLEN = 2 + IPT;
constexpr int HH = H * H;
constexpr long long HSEQ_ELEMS = (long long)B * T * S * H;
constexpr long long HC_ELEMS   = (long long)B * S * H;
// dynamic smem layout (float offsets) — weights resident
constexpr int SM_W1  = 0;
constexpr int SM_W2  = SM_W1 + HH;
constexpr int SM_W3  = SM_W2 + HH;
constexpr int SM_HT  = SM_W3 + HH;          // [128][12]
constexpr int SM_BUF = SM_HT + H * 12;      // [128][12]
constexpr int SM_QPS = SM_BUF + H * 12;     // [10][128]
constexpr int SM_SSM = SM_QPS + S * H;      // ssmT [64][12]
constexpr int SM_ST2 = SM_SSM + T * 12;     // [10][128]
constexpr int SM_ST3 = SM_ST2 + S * H;      // [10][128]
constexpr int SM_ATS = SM_ST3 + S * H;      // [6][128]
constexpr int SM_TOTAL = SM_ATS + 6 * H;    // 57600 floats = 230400 B
}

// ---------------- scratch ----------------
__device__ float g_qp[B * T * S * H];
__device__ float g_A [B * T * H * 6];       // [B,T,H,6]: a0,a1,a2,a3,td1,td2
__device__ float g_pk[B * T * S * H];
__device__ float g_pv[B * T * S * H];
__device__ float g_Wc[H * H];
__device__ float g_bc[H];
__device__ float2 g_Wh01[H * H];
__device__ float2 g_Wh23[H * H];
__device__ float g_nvinv[T];
__device__ float g_lpart[B * T];
__device__ int   g_perm[B];

// ---------------- f32x2 helpers ----------------
using u64 = unsigned long long;
__device__ __forceinline__ u64 pk2(float lo, float hi) {
    u64 r; asm("mov.b64 %0,{%1,%2};" : "=l"(r) : "f"(lo), "f"(hi)); return r;
}
__device__ __forceinline__ u64 dup2(float x) { return pk2(x, x); }
__device__ __forceinline__ void un2(u64 v, float& a, float& b) {
    asm("mov.b64 {%0,%1},%2;" : "=f"(a), "=f"(b) : "l"(v));
}
__device__ __forceinline__ void fma2(u64& d, u64 a, u64 b) {
    asm("fma.rn.f32x2 %0,%1,%2,%0;" : "+l"(d) : "l"(a), "l"(b));
}

__device__ __forceinline__ float sigf(float x) {
    return __fdividef(1.f, 1.f + __expf(-x));
}
__device__ __forceinline__ float tanhfast(float x) {
    return __fdividef(2.f, 1.f + __expf(-2.f * x)) - 1.f;
}

// ---------------- fold: q-weights + Wh interleave + perm/nvinv ----------------
__global__ void __launch_bounds__(128) fold_kernel(
    const float* __restrict__ Wa, const float* __restrict__ ba,
    const float* __restrict__ Wattn, const float* __restrict__ battn,
    const float* __restrict__ Wh, const int* __restrict__ keys_length)
{
    const int bx = blockIdx.x, tid = threadIdx.x;
    if (bx < 128) {
        const int q = bx, h = tid;
        const float scale = 0.08838834764831845f;
        float acc = 0.f;
        for (int j = 0; j < H; ++j) acc += Wa[q * H + j] * Wattn[j * H + h];
        g_Wc[q * H + h] = acc * scale;
        if (q == 0) {
            float bacc = battn[h];
            for (int j = 0; j < H; ++j) bacc += ba[j] * Wattn[j * H + h];
            g_bc[h] = bacc * scale;
        }
        return;
    }
    const int e = (bx - 128) * 128 + tid;
    g_Wh01[e] = make_float2(Wh[e], Wh[HH + e]);
    g_Wh23[e] = make_float2(Wh[2 * HH + e], Wh[3 * HH + e]);

    if (bx == 128) {
#pragma unroll
        for (int half = 0; half < 2; ++half) {
            const int b = tid + half * 128;
            const int kb = keys_length[b];
            int rank = 0;
            for (int j = 0; j < B; ++j) {
                const int kj = keys_length[j];
                rank += (kj > kb) || (kj == kb && j < b);
            }
            g_perm[rank] = b;
        }
        if (tid < T) {
            int cnt = 0;
            for (int j = 0; j < B; ++j) cnt += (tid < keys_length[j]) ? 1 : 0;
            g_nvinv[tid] = cnt ? 1.f / (float)cnt : 0.f;
        }
    }
}

// ---------------- precompute A[B,T,H,6] (only t < kl) ----------------
__global__ void __launch_bounds__(128) pre_kernel(
    const float* __restrict__ inputs, const float* __restrict__ Wx,
    const float* __restrict__ Wts, const float* __restrict__ bg,
    const int* __restrict__ keys_length)
{
    const int b = blockIdx.x, k = threadIdx.x;
    const int kl = keys_length[b];
    if (kl == 0) return;
    __shared__ float xsT[IPT][66];
    __shared__ float Tts[T], Dts[T];
    const int tmax = kl;
    for (int idx = k; idx < tmax * IPT; idx += 128) {
        const int t = idx >> 7, i = idx & 127;
        xsT[i][t] = inputs[(long long)(b * T + t) * ROWLEN + 2 + i];
    }
    if (k < tmax) {
        Tts[k] = inputs[(long long)(b * T + k) * ROWLEN + 0];
        Dts[k] = inputs[(long long)(b * T + k) * ROWLEN + 1];
    }
    __syncthreads();

    const float wt0 = Wts[0 * H + k], wt1 = Wts[1 * H + k];
    const float wt2 = Wts[2 * H + k], wt3 = Wts[3 * H + k];
    const float wt4 = Wts[4 * H + k], wt5 = Wts[5 * H + k];
    float bgv[8];
#pragma unroll
    for (int g = 0; g < 8; ++g) bgv[g] = bg[g * H + k];

    for (int t0 = 0; t0 < tmax; t0 += 16) {
        const int nt = min(16, tmax - t0);
        float T1v[16], T2v[16];
#pragma unroll
        for (int g = 0; g < 8; ++g) {
            u64 acc[8];
#pragma unroll
            for (int j = 0; j < 8; ++j) acc[j] = 0ull;
            const float* Wg = Wx + (long long)g * IPT * H + k;
#pragma unroll 4
            for (int i = 0; i < IPT; ++i) {
                const u64 wd = dup2(Wg[(long long)i * H]);
#pragma unroll
                for (int j = 0; j < 8; ++j)
                    fma2(acc[j], *(const u64*)&xsT[i][t0 + 2 * j], wd);
            }
#pragma unroll
            for (int j = 0; j < 8; ++j) {
                float v0, v1; un2(acc[j], v0, v1);
#pragma unroll
                for (int half = 0; half < 2; ++half) {
                    const int tt = 2 * j + half;
                    if (tt >= nt) continue;
                    const int t = t0 + tt;
                    const float v = half ? v1 : v0;
                    float* At = g_A + (((long long)(b * T + t)) * H + k) * 6;
                    if (g == 0)      At[0] = v + bgv[0];
                    else if (g == 1) At[1] = v + bgv[1];
                    else if (g == 2) At[2] = v + bgv[2];
                    else if (g == 3) At[3] = v + Tts[t] * wt4 + Dts[t] * wt5 + bgv[3];
                    else if (g == 4) T1v[tt] = sigf(v + sigf(Tts[t] * wt0) + bgv[4]);
                    else if (g == 5) T2v[tt] = sigf(v + sigf(Tts[t] * wt1) + bgv[5]);
                    else if (g == 6) At[4] = T1v[tt] * sigf(v + sigf(Dts[t] * wt2) + bgv[6]);
                    else             At[5] = T2v[tt] * sigf(v + sigf(Dts[t] * wt3) + bgv[7]);
                }
            }
        }
    }
}

// ---------------- qp = x_q @ Wc + bc (only 1 <= t < kl) ----------------
__global__ void __launch_bounds__(128) qp_kernel(
    const float* __restrict__ x_q, const int* __restrict__ keys_length)
{
    const int bt = blockIdx.x, k = threadIdx.x;
    const int b = bt >> 6, t = bt & 63;
    if (t == 0 || t >= keys_length[b]) return;
    __shared__ float xqT[Q][12];
    const float* xp = x_q + (long long)bt * S * Q;
    for (int idx = k; idx < S * Q; idx += 128) {
        const int s = idx >> 7, q = idx & 127;
        xqT[q][s] = xp[idx];
    }
    __syncthreads();
    const float bcv = g_bc[k];
    u64 acc[5];
#pragma unroll
    for (int p = 0; p < 5; ++p) acc[p] = dup2(bcv);
#pragma unroll 4
    for (int i = 0; i < Q; ++i) {
        const u64 wd = dup2(g_Wc[i * H + k]);
#pragma unroll
        for (int p = 0; p < 5; ++p)
            fma2(acc[p], *(const u64*)&xqT[i][2 * p], wd);
    }
    float* o = g_qp + (long long)bt * S * H + k;
#pragma unroll
    for (int p = 0; p < 5; ++p) {
        float v0, v1; un2(acc[p], v0, v1);
        o[(2 * p) * H] = v0; o[(2 * p + 1) * H] = v1;
    }
}

// ---------------- recurrent kernel ----------------
__global__ void __launch_bounds__(256, 1) rec_kernel(
    const float* __restrict__ Wattn, const float* __restrict__ battn,
    const int* __restrict__ keys_length, float* __restrict__ out)
{
    extern __shared__ float sm[];
    const int tid = threadIdx.x;
    const int k = tid & 127, half = tid >> 7;
    const int lane = tid & 31, warp = tid >> 5;
    const int b = g_perm[blockIdx.x];
    const int kl = keys_length[b];

    {
        const float4* src = (const float4*)(Wattn + HH);
        float4* dst = (float4*)(sm + SM_W1);
        for (int i = tid; i < 3 * HH / 4; i += 256) dst[i] = src[i];
    }
    for (int i = tid; i < 2 * H * 12; i += 256) sm[SM_HT + i] = 0.f;
    __syncthreads();

    float* hT   = sm + SM_HT;
    float* bufT = sm + SM_BUF;

    const float b1v = battn[1 * H + k];
    const float b2v = battn[2 * H + k];
    const float b3v = battn[3 * H + k];

    float c[S];
#pragma unroll
    for (int s = 0; s < S; ++s) c[s] = 0.f;

    int t = 0;
    for (; t < kl; ++t) {
        // ---- phase A: prefetch cell inputs (half0, 3x LDG.64) + load qp ----
        float a0 = 0.f, a1 = 0.f, a2 = 0.f, a3 = 0.f, td1 = 0.f, td2 = 0.f;
        if (half == 0) {
            const float* Ab = g_A + (((long long)(b * T + t)) * H + k) * 6;
            const float2 x01 = *(const float2*)(Ab);
            const float2 x23 = *(const float2*)(Ab + 2);
            const float2 x45 = *(const float2*)(Ab + 4);
            a0 = x01.x; a1 = x01.y; a2 = x23.x; a3 = x23.y;
            td1 = x45.x; td2 = x45.y;
        }
        if (t > 0) {
            const float* qpp = g_qp + ((long long)(b * T + t) * S) * H;
#pragma unroll
            for (int j = 0; j < 5; ++j) {
                const int s = half * 5 + j;
                sm[SM_QPS + s * H + k] = qpp[s * H + k];
            }
        }
        __syncthreads();

        if (t > 0) {
            // ---- phase B: flat-index scores + exp at store (transposed out) ----
            const int group = tid >> 3, gl = tid & 7;
            const int nd = S * t;
            const int iters = (nd + 31) >> 5;
            const float tinv = __fdividef(1.f, (float)t);
            for (int i = 0; i < iters; ++i) {
                const int idx = group + 32 * i;
                const bool valid = idx < nd;
                int s = 0, tp = 0;
                float acc = 0.f;
                if (valid) {
                    s = (int)(((float)idx + 0.5f) * tinv);
                    tp = idx - s * t;
                    const float4* pkr = (const float4*)(g_pk + ((long long)((b * T + tp) * S + s)) * H) + gl * 4;
                    const float4* qr  = (const float4*)(sm + SM_QPS + s * H) + gl * 4;
#pragma unroll
                    for (int j = 0; j < 4; ++j) {
                        const float4 q = qr[j], p = pkr[j];
                        acc += q.x * p.x + q.y * p.y + q.z * p.z + q.w * p.w;
                    }
                }
                acc += __shfl_xor_sync(0xffffffffu, acc, 1);
                acc += __shfl_xor_sync(0xffffffffu, acc, 2);
                acc += __shfl_xor_sync(0xffffffffu, acc, 4);
                if (valid && gl == 0) sm[SM_SSM + tp * 12 + s] = __expf(acc);
            }
            __syncthreads();

            // ---- phase C: normalize per s (strided rows, small) ----
            for (int s = warp; s < S; s += 8) {
                float sum = 0.f;
                for (int tp = lane; tp < t; tp += 32) sum += sm[SM_SSM + tp * 12 + s];
#pragma unroll
                for (int o = 16; o > 0; o >>= 1) sum += __shfl_xor_sync(0xffffffffu, sum, o);
                const float inv = __fdividef(1.f, sum);
                for (int tp = lane; tp < t; tp += 32) sm[SM_SSM + tp * 12 + s] *= inv;
            }
            __syncthreads();

            // ---- phase D: ctx, s-split 4/6, vector prob loads ----
            if (half == 0) {
                float cx[4] = {0.f, 0.f, 0.f, 0.f};
                const float* pvb = g_pv + ((long long)b * T * S) * H + k;
#pragma unroll 8
                for (int tp = 0; tp < t; ++tp) {
                    const float4 pr = *(const float4*)(sm + SM_SSM + tp * 12);
                    const float* pvr = pvb + (long long)tp * S * H;
                    cx[0] += pr.x * pvr[0];
                    cx[1] += pr.y * pvr[H];
                    cx[2] += pr.z * pvr[2 * H];
                    cx[3] += pr.w * pvr[3 * H];
                }
#pragma unroll
                for (int s = 0; s < 4; ++s) bufT[k * 12 + s] = cx[s];
            } else {
                float cx[6] = {0.f, 0.f, 0.f, 0.f, 0.f, 0.f};
                const float* pvb = g_pv + ((long long)b * T * S) * H + k + 4 * H;
#pragma unroll 8
                for (int tp = 0; tp < t; ++tp) {
                    const float4 pa = *(const float4*)(sm + SM_SSM + tp * 12 + 4);
                    const float2 pb = *(const float2*)(sm + SM_SSM + tp * 12 + 8);
                    const float* pvr = pvb + (long long)tp * S * H;
                    cx[0] += pa.x * pvr[0];
                    cx[1] += pa.y * pvr[H];
                    cx[2] += pa.z * pvr[2 * H];
                    cx[3] += pa.w * pvr[3 * H];
                    cx[4] += pb.x * pvr[4 * H];
                    cx[5] += pb.y * pvr[5 * H];
                }
#pragma unroll
                for (int s = 0; s < 6; ++s) bufT[k * 12 + 4 + s] = cx[s];
            }
            __syncthreads();
        }

        // ---- phase E: combined gate + at GEMMs (vectorized smem reads) ----
        u64 A0[5], A1[5], At2[2];     // half0
        if (half == 0) {
#pragma unroll
            for (int p = 0; p < 5; ++p) { A0[p] = 0ull; A1[p] = 0ull; }
            At2[0] = dup2(b3v); At2[1] = dup2(b3v);
            const float2* Wp = g_Wh01 + k;
#pragma unroll 8
            for (int h = 0; h < H; ++h) {
                const float2 w01 = Wp[h * H];
                const u64 w0 = dup2(w01.x);
                const u64 w1 = dup2(w01.y);
                const u64 w3 = dup2(sm[SM_W3 + h * H + k]);
                const float* hr = hT + h * 12;
                const float4 ha = *(const float4*)(hr);
                const float4 hb = *(const float4*)(hr + 4);
                const float2 hc = *(const float2*)(hr + 8);
                u64 hp[5];
                hp[0] = pk2(ha.x, ha.y); hp[1] = pk2(ha.z, ha.w);
                hp[2] = pk2(hb.x, hb.y); hp[3] = pk2(hb.z, hb.w);
                hp[4] = pk2(hc.x, hc.y);
#pragma unroll
                for (int p = 0; p < 5; ++p) {
                    fma2(A0[p], hp[p], w0); fma2(A1[p], hp[p], w1);
                }
                const float4 bv = *(const float4*)(bufT + h * 12);
                fma2(At2[0], pk2(bv.x, bv.y), w3);
                fma2(At2[1], pk2(bv.z, bv.w), w3);
            }
        } else {
            u64 A2[5], A3[5], At3[3];
#pragma unroll
            for (int p = 0; p < 5; ++p) { A2[p] = 0ull; A3[p] = 0ull; }
#pragma unroll
            for (int j = 0; j < 3; ++j) At3[j] = dup2(b3v);
            const float2* Wp = g_Wh23 + k;
#pragma unroll 8
            for (int h = 0; h < H; ++h) {
                const float2 w23 = Wp[h * H];
                const u64 w2  = dup2(w23.x);
                const u64 w3g = dup2(w23.y);
                const u64 w3a = dup2(sm[SM_W3 + h * H + k]);
                const float* hr = hT + h * 12;
                const float4 ha = *(const float4*)(hr);
                const float4 hb = *(const float4*)(hr + 4);
                const float2 hc = *(const float2*)(hr + 8);
                u64 hp[5];
                hp[0] = pk2(ha.x, ha.y); hp[1] = pk2(ha.z, ha.w);
                hp[2] = pk2(hb.x, hb.y); hp[3] = pk2(hb.z, hb.w);
                hp[4] = pk2(hc.x, hc.y);
#pragma unroll
                for (int p = 0; p < 5; ++p) {
                    fma2(A2[p], hp[p], w2); fma2(A3[p], hp[p], w3g);
                }
                const float4 bv = *(const float4*)(bufT + h * 12 + 4);
                const float2 bw = *(const float2*)(bufT + h * 12 + 8);
                fma2(At3[0], pk2(bv.x, bv.y), w3a);
                fma2(At3[1], pk2(bv.z, bv.w), w3a);
                fma2(At3[2], pk2(bw.x, bw.y), w3a);
            }
#pragma unroll
            for (int p = 0; p < 5; ++p) {
                float v0, v1;
                un2(A2[p], v0, v1);
                sm[SM_ST2 + (2 * p) * H + k] = v0; sm[SM_ST2 + (2 * p + 1) * H + k] = v1;
                un2(A3[p], v0, v1);
                sm[SM_ST3 + (2 * p) * H + k] = v0; sm[SM_ST3 + (2 * p + 1) * H + k] = v1;
            }
#pragma unroll
            for (int j = 0; j < 3; ++j) {
                float v0, v1; un2(At3[j], v0, v1);
                sm[SM_ATS + (2 * j) * H + k] = v0; sm[SM_ATS + (2 * j + 1) * H + k] = v1;
            }
        }
        __syncthreads();

        // ---- phase F: cell (half0 only, loss-free) ----
        if (half == 0) {
            float G0[S], G1[S], at0[4];
#pragma unroll
            for (int p = 0; p < 5; ++p) {
                un2(A0[p], G0[2 * p], G0[2 * p + 1]);
                un2(A1[p], G1[2 * p], G1[2 * p + 1]);
            }
            un2(At2[0], at0[0], at0[1]);
            un2(At2[1], at0[2], at0[3]);
#pragma unroll
            for (int s = 0; s < S; ++s) {
                const float g2 = sm[SM_ST2 + s * H + k];
                const float g3 = sm[SM_ST3 + s * H + k];
                float atv = 1.f;
                if (t > 0) atv = (s < 4) ? at0[s] : sm[SM_ATS + (s - 4) * H + k];
                const float it = sigf(a0 + G0[s]);
                const float ft = sigf(a1 + G1[s]);
                const float ct = tanhfast(a2 + g2);
                const float ot = sigf(a3 + g3);
                const float itp = it * atv, ftp = ft * atv;
                const float fc = ftp * c[s];
                const float ic = itp * ct;
                const float chat = fc + ic * td1;
                c[s] = fc + ic * td2;
                hT[k * 12 + s] = ot * tanhfast(chat);
            }
        }
        __syncthreads();

        // ---- phase G: pk / pv GEMMs + output (vectorized) ----
        if (half == 0) {
            u64 P[5];
#pragma unroll
            for (int p = 0; p < 5; ++p) P[p] = dup2(b1v);
#pragma unroll 8
            for (int h = 0; h < H; ++h) {
                const u64 w = dup2(sm[SM_W1 + h * H + k]);
                const float* hr = hT + h * 12;
                const float4 ha = *(const float4*)(hr);
                const float4 hb = *(const float4*)(hr + 4);
                const float2 hc = *(const float2*)(hr + 8);
                fma2(P[0], pk2(ha.x, ha.y), w);
                fma2(P[1], pk2(ha.z, ha.w), w);
                fma2(P[2], pk2(hb.x, hb.y), w);
                fma2(P[3], pk2(hb.z, hb.w), w);
                fma2(P[4], pk2(hc.x, hc.y), w);
            }
            float* pkp = g_pk + ((long long)((b * T + t) * S)) * H + k;
#pragma unroll
            for (int p = 0; p < 5; ++p) {
                float v0, v1; un2(P[p], v0, v1);
                pkp[(2 * p) * H] = v0; pkp[(2 * p + 1) * H] = v1;
            }
        } else {
            u64 P[5];
#pragma unroll
            for (int p = 0; p < 5; ++p) P[p] = dup2(b2v);
#pragma unroll 8
            for (int h = 0; h < H; ++h) {
                const u64 w = dup2(sm[SM_W2 + h * H + k]);
                const float* hr = hT + h * 12;
                const float4 ha = *(const float4*)(hr);
                const float4 hb = *(const float4*)(hr + 4);
                const float2 hc = *(const float2*)(hr + 8);
                fma2(P[0], pk2(ha.x, ha.y), w);
                fma2(P[1], pk2(ha.z, ha.w), w);
                fma2(P[2], pk2(hb.x, hb.y), w);
                fma2(P[3], pk2(hb.z, hb.w), w);
                fma2(P[4], pk2(hc.x, hc.y), w);
            }
            float* pvp = g_pv + ((long long)((b * T + t) * S)) * H + k;
#pragma unroll
            for (int p = 0; p < 5; ++p) {
                float v0, v1; un2(P[p], v0, v1);
                pvp[(2 * p) * H] = v0; pvp[(2 * p + 1) * H] = v1;
            }
            float* outp = out + ((long long)((b * T + t) * S)) * H + k;
#pragma unroll
            for (int s = 0; s < S; ++s) outp[s * H] = hT[k * 12 + s];
        }
        __syncthreads();
    }

    // masked steps: zeros
    for (; t < T; ++t) {
        float* outp = out + ((long long)((b * T + t) * S)) * H + k;
#pragma unroll
        for (int j = 0; j < 5; ++j) outp[(half * 5 + j) * H] = 0.f;
    }

    // final h, c
    if (half == 0) {
        float* oh = out + HSEQ_ELEMS + ((long long)b * S) * H + k;
#pragma unroll
        for (int s = 0; s < S; ++s) oh[s * H] = hT[k * 12 + s];
        float* oc = oh + HC_ELEMS;
#pragma unroll
        for (int s = 0; s < S; ++s) oc[s * H] = c[s];
    }
}

// ---------------- bce: loss from hseq (parallel post-pass) ----------------
__global__ void __launch_bounds__(128) bce_kernel(
    const float* __restrict__ out, const float* __restrict__ austgn_y,
    const int* __restrict__ keys_length)
{
    const int bt = blockIdx.x;
    const int b = bt >> 6, t = bt & 63;
    const int k = threadIdx.x;
    __shared__ float red[4];
    if (t >= keys_length[b]) {
        if (k == 0) g_lpart[bt] = 0.f;
        return;
    }
    const float y = austgn_y[bt];
    const float* hp = out + ((long long)bt * S) * H + k;
    float bsum = 0.f;
#pragma unroll
    for (int s = 0; s < S; ++s) {
        const float hn = hp[s * H];
        const float p = fminf(fmaxf(hn, 1e-7f), 1.f - 1e-7f);
        bsum += -(y * __logf(p) + (1.f - y) * __logf(1.f - p));
    }
#pragma unroll
    for (int o = 16; o > 0; o >>= 1) bsum += __shfl_xor_sync(0xffffffffu, bsum, o);
    if ((k & 31) == 0) red[k >> 5] = bsum;
    __syncthreads();
    if (k == 0)
        g_lpart[bt] = (red[0] + red[1] + red[2] + red[3]) * g_nvinv[t] * (1.f / (float)(S * H));
}

// ---------------- final deterministic loss reduction ----------------
__global__ void __launch_bounds__(256) loss_kernel(float* __restrict__ out)
{
    __shared__ float smr[256];
    const int i = threadIdx.x;
    float sum = 0.f;
    for (int j = 0; j < 64; ++j) sum += g_lpart[i * 64 + j];
    smr[i] = sum;
    __syncthreads();
    for (int off = 128; off > 0; off >>= 1) {
        if (i < off) smr[i] += smr[i + off];
        __syncthreads();
    }
    if (i == 0) out[HSEQ_ELEMS + 2 * HC_ELEMS] = smr[0];
}

// ---------------- launch ----------------
extern "C" void kernel_launch(void* const* d_in, const int* in_sizes, int n_in,
                              void* d_out, int out_size)
{
    (void)in_sizes; (void)n_in; (void)out_size;
    const float* inputs      = (const float*)d_in[0];
    const float* x_q         = (const float*)d_in[1];
    const float* austgn_y    = (const float*)d_in[2];
    const int*   keys_length = (const int*)  d_in[3];
    const float* Wx          = (const float*)d_in[4];
    const float* Wh          = (const float*)d_in[5];
    const float* Wts         = (const float*)d_in[6];
    const float* bg          = (const float*)d_in[7];
    const float* Wa          = (const float*)d_in[8];
    const float* ba          = (const float*)d_in[9];
    const float* Wattn       = (const float*)d_in[10];
    const float* battn       = (const float*)d_in[11];
    float* out = (float*)d_out;

    static int smem_set = 0;
    if (!smem_set) {
        cudaFuncSetAttribute(rec_kernel, cudaFuncAttributeMaxDynamicSharedMemorySize,
                             SM_TOTAL * (int)sizeof(float));
        smem_set = 1;
    }

    fold_kernel<<<256, 128>>>(Wa, ba, Wattn, battn, Wh, keys_length);
    pre_kernel<<<B, 128>>>(inputs, Wx, Wts, bg, keys_length);
    qp_kernel<<<B * T, 128>>>(x_q, keys_length);
    rec_kernel<<<B, 256, SM_TOTAL * (int)sizeof(float)>>>(
        Wattn, battn, keys_length, out);
    bce_kernel<<<B * T, 128>>>(out, austgn_y, keys_length);
    loss_kernel<<<1, 256>>>(out);
}

// round 12
// speedup vs baseline: 1.2587x; 1.0103x over previous
#include <cuda_runtime.h>
#include <math.h>

namespace {
constexpr int B = 256, T = 64, S = 10, H = 128, IPT = 128, Q = 128;
constexpr int ROWLEN = 2 + IPT;
constexpr int HH = H * H;
constexpr long long HSEQ_ELEMS = (long long)B * T * S * H;
constexpr long long HC_ELEMS   = (long long)B * S * H;
// dynamic smem layout (float offsets)
constexpr int SM_W1  = 0;                   // [128][128]
constexpr int SM_W2  = SM_W1 + HH;
constexpr int SM_W3  = SM_W2 + HH;
constexpr int SM_HT  = SM_W3 + HH;          // [128][12]
constexpr int SM_BUF = SM_HT + H * 12;      // [128][12]
constexpr int SM_QPS = SM_BUF + H * 12;     // [2][10][128] double-buffered
constexpr int SM_SSM = SM_QPS + 2 * S * H;  // ssmT [64][12]
constexpr int SM_ATS = SM_SSM + T * 12;     // [10][128]
constexpr int SM_INV = SM_ATS + S * H;      // [16]
constexpr int SM_TOTAL = SM_INV + 16;       // 56848 floats = 227392 B
}

// ---------------- scratch ----------------
__device__ float g_qp[B * T * S * H];
__device__ float g_A [B * T * H * 6];       // [B,T,H,6]: a0,a1,a2,a3,td1,td2
__device__ float g_pk[B * T * S * H];
__device__ float g_pv[B * T * S * H];
__device__ float g_Wc[H * H];
__device__ float g_bc[H];
__device__ float2 g_Wh01[H * H];
__device__ float2 g_Wh23[H * H];
__device__ float g_nvinv[T];
__device__ float g_lpart[B * T];
__device__ int   g_perm[B];

// ---------------- f32x2 helpers ----------------
using u64 = unsigned long long;
__device__ __forceinline__ u64 pk2(float lo, float hi) {
    u64 r; asm("mov.b64 %0,{%1,%2};" : "=l"(r) : "f"(lo), "f"(hi)); return r;
}
__device__ __forceinline__ u64 dup2(float x) { return pk2(x, x); }
__device__ __forceinline__ void un2(u64 v, float& a, float& b) {
    asm("mov.b64 {%0,%1},%2;" : "=f"(a), "=f"(b) : "l"(v));
}
__device__ __forceinline__ void fma2(u64& d, u64 a, u64 b) {
    asm("fma.rn.f32x2 %0,%1,%2,%0;" : "+l"(d) : "l"(a), "l"(b));
}

__device__ __forceinline__ float sigf(float x) {
    return __fdividef(1.f, 1.f + __expf(-x));
}
__device__ __forceinline__ float tanhfast(float x) {
    return __fdividef(2.f, 1.f + __expf(-2.f * x)) - 1.f;
}

// ---------------- fold: q-weights + Wh interleave + perm/nvinv ----------------
__global__ void __launch_bounds__(128) fold_kernel(
    const float* __restrict__ Wa, const float* __restrict__ ba,
    const float* __restrict__ Wattn, const float* __restrict__ battn,
    const float* __restrict__ Wh, const int* __restrict__ keys_length)
{
    const int bx = blockIdx.x, tid = threadIdx.x;
    if (bx < 128) {
        const int q = bx, h = tid;
        const float scale = 0.08838834764831845f;
        float acc = 0.f;
        for (int j = 0; j < H; ++j) acc += Wa[q * H + j] * Wattn[j * H + h];
        g_Wc[q * H + h] = acc * scale;
        if (q == 0) {
            float bacc = battn[h];
            for (int j = 0; j < H; ++j) bacc += ba[j] * Wattn[j * H + h];
            g_bc[h] = bacc * scale;
        }
        return;
    }
    const int e = (bx - 128) * 128 + tid;
    g_Wh01[e] = make_float2(Wh[e], Wh[HH + e]);
    g_Wh23[e] = make_float2(Wh[2 * HH + e], Wh[3 * HH + e]);

    if (bx == 128) {
#pragma unroll
        for (int half = 0; half < 2; ++half) {
            const int b = tid + half * 128;
            const int kb = keys_length[b];
            int rank = 0;
            for (int j = 0; j < B; ++j) {
                const int kj = keys_length[j];
                rank += (kj > kb) || (kj == kb && j < b);
            }
            g_perm[rank] = b;
        }
        if (tid < T) {
            int cnt = 0;
            for (int j = 0; j < B; ++j) cnt += (tid < keys_length[j]) ? 1 : 0;
            g_nvinv[tid] = cnt ? 1.f / (float)cnt : 0.f;
        }
    }
}

// ---------------- precompute A[B,T,H,6] (only t < kl) ----------------
__global__ void __launch_bounds__(128) pre_kernel(
    const float* __restrict__ inputs, const float* __restrict__ Wx,
    const float* __restrict__ Wts, const float* __restrict__ bg,
    const int* __restrict__ keys_length)
{
    const int b = blockIdx.x, k = threadIdx.x;
    const int kl = keys_length[b];
    if (kl == 0) return;
    __shared__ float xsT[IPT][66];
    __shared__ float Tts[T], Dts[T];
    const int tmax = kl;
    for (int idx = k; idx < tmax * IPT; idx += 128) {
        const int t = idx >> 7, i = idx & 127;
        xsT[i][t] = inputs[(long long)(b * T + t) * ROWLEN + 2 + i];
    }
    if (k < tmax) {
        Tts[k] = inputs[(long long)(b * T + k) * ROWLEN + 0];
        Dts[k] = inputs[(long long)(b * T + k) * ROWLEN + 1];
    }
    __syncthreads();

    const float wt0 = Wts[0 * H + k], wt1 = Wts[1 * H + k];
    const float wt2 = Wts[2 * H + k], wt3 = Wts[3 * H + k];
    const float wt4 = Wts[4 * H + k], wt5 = Wts[5 * H + k];
    float bgv[8];
#pragma unroll
    for (int g = 0; g < 8; ++g) bgv[g] = bg[g * H + k];

    for (int t0 = 0; t0 < tmax; t0 += 16) {
        const int nt = min(16, tmax - t0);
        float T1v[16], T2v[16];
#pragma unroll
        for (int g = 0; g < 8; ++g) {
            u64 acc[8];
#pragma unroll
            for (int j = 0; j < 8; ++j) acc[j] = 0ull;
            const float* Wg = Wx + (long long)g * IPT * H + k;
#pragma unroll 4
            for (int i = 0; i < IPT; ++i) {
                const u64 wd = dup2(Wg[(long long)i * H]);
#pragma unroll
                for (int j = 0; j < 8; ++j)
                    fma2(acc[j], *(const u64*)&xsT[i][t0 + 2 * j], wd);
            }
#pragma unroll
            for (int j = 0; j < 8; ++j) {
                float v0, v1; un2(acc[j], v0, v1);
#pragma unroll
                for (int half = 0; half < 2; ++half) {
                    const int tt = 2 * j + half;
                    if (tt >= nt) continue;
                    const int t = t0 + tt;
                    const float v = half ? v1 : v0;
                    float* At = g_A + (((long long)(b * T + t)) * H + k) * 6;
                    if (g == 0)      At[0] = v + bgv[0];
                    else if (g == 1) At[1] = v + bgv[1];
                    else if (g == 2) At[2] = v + bgv[2];
                    else if (g == 3) At[3] = v + Tts[t] * wt4 + Dts[t] * wt5 + bgv[3];
                    else if (g == 4) T1v[tt] = sigf(v + sigf(Tts[t] * wt0) + bgv[4]);
                    else if (g == 5) T2v[tt] = sigf(v + sigf(Tts[t] * wt1) + bgv[5]);
                    else if (g == 6) At[4] = T1v[tt] * sigf(v + sigf(Dts[t] * wt2) + bgv[6]);
                    else             At[5] = T2v[tt] * sigf(v + sigf(Dts[t] * wt3) + bgv[7]);
                }
            }
        }
    }
}

// ---------------- qp = x_q @ Wc + bc (only 1 <= t < kl) ----------------
__global__ void __launch_bounds__(128) qp_kernel(
    const float* __restrict__ x_q, const int* __restrict__ keys_length)
{
    const int bt = blockIdx.x, k = threadIdx.x;
    const int b = bt >> 6, t = bt & 63;
    if (t == 0 || t >= keys_length[b]) return;
    __shared__ float xqT[Q][12];
    const float* xp = x_q + (long long)bt * S * Q;
    for (int idx = k; idx < S * Q; idx += 128) {
        const int s = idx >> 7, q = idx & 127;
        xqT[q][s] = xp[idx];
    }
    __syncthreads();
    const float bcv = g_bc[k];
    u64 acc[5];
#pragma unroll
    for (int p = 0; p < 5; ++p) acc[p] = dup2(bcv);
#pragma unroll 4
    for (int i = 0; i < Q; ++i) {
        const u64 wd = dup2(g_Wc[i * H + k]);
#pragma unroll
        for (int p = 0; p < 5; ++p)
            fma2(acc[p], *(const u64*)&xqT[i][2 * p], wd);
    }
    float* o = g_qp + (long long)bt * S * H + k;
#pragma unroll
    for (int p = 0; p < 5; ++p) {
        float v0, v1; un2(acc[p], v0, v1);
        o[(2 * p) * H] = v0; o[(2 * p + 1) * H] = v1;
    }
}

// ---------------- recurrent kernel: warp-group specialized ----------------
__global__ void __launch_bounds__(256, 1) rec_kernel(
    const float* __restrict__ Wattn, const float* __restrict__ battn,
    const int* __restrict__ keys_length, float* __restrict__ out)
{
    extern __shared__ float sm[];
    const int tid = threadIdx.x;
    const int k = tid & 127, wg = tid >> 7;    // wg0=attn, wg1=gate
    const int lane = tid & 31, warp = tid >> 5;
    const int b = g_perm[blockIdx.x];
    const int kl = keys_length[b];

    {
        const float4* src = (const float4*)(Wattn + HH);
        float4* dst = (float4*)(sm + SM_W1);
        for (int i = tid; i < 3 * HH / 4; i += 256) dst[i] = src[i];
    }
    for (int i = tid; i < 2 * H * 12; i += 256) sm[SM_HT + i] = 0.f;
    __syncthreads();

    float* hT   = sm + SM_HT;
    float* bufT = sm + SM_BUF;

    const float b1v = battn[1 * H + k];
    const float b2v = battn[2 * H + k];
    const float b3v = battn[3 * H + k];

    float c[S];
#pragma unroll
    for (int s = 0; s < S; ++s) c[s] = 0.f;

    int t = 0;
    for (; t < kl; ++t) {
        // ===================== parallel section =====================
        u64 A0[5], A1[5], A2[5], A3[5];      // gate accumulators (wg1)
        float a0 = 0.f, a1 = 0.f, a2 = 0.f, a3 = 0.f, td1 = 0.f, td2 = 0.f;

        if (wg == 0) {
            // ---------- attention warps ----------
            if (t > 0) {
                // B': scores + exp, flat 16-octet indexing
                const int group = tid >> 3, gl = tid & 7;
                const int nd = S * t;
                const int iters = (nd + 15) >> 4;
                const float tinv = __fdividef(1.f, (float)t);
                const float* qbase = sm + SM_QPS + (t & 1) * (S * H);
                for (int i = 0; i < iters; ++i) {
                    const int idx = group + 16 * i;
                    const bool valid = idx < nd;
                    int s = 0, tp = 0;
                    float acc = 0.f;
                    if (valid) {
                        s = (int)(((float)idx + 0.5f) * tinv);
                        tp = idx - s * t;
                        const float4* pkr = (const float4*)(g_pk + ((long long)((b * T + tp) * S + s)) * H) + gl * 4;
                        const float4* qr  = (const float4*)(qbase + s * H) + gl * 4;
#pragma unroll
                        for (int j = 0; j < 4; ++j) {
                            const float4 q = qr[j], p = pkr[j];
                            acc += q.x * p.x + q.y * p.y + q.z * p.z + q.w * p.w;
                        }
                    }
                    acc += __shfl_xor_sync(0xffffffffu, acc, 1);
                    acc += __shfl_xor_sync(0xffffffffu, acc, 2);
                    acc += __shfl_xor_sync(0xffffffffu, acc, 4);
                    if (valid && gl == 0) sm[SM_SSM + tp * 12 + s] = __expf(acc);
                }
                asm volatile("bar.sync 1, 128;" ::: "memory");

                // C': row sums -> inverse only (no write-back)
                for (int s = warp; s < S; s += 4) {
                    float sum = 0.f;
                    for (int tp = lane; tp < t; tp += 32) sum += sm[SM_SSM + tp * 12 + s];
#pragma unroll
                    for (int o = 16; o > 0; o >>= 1) sum += __shfl_xor_sync(0xffffffffu, sum, o);
                    if (lane == 0) sm[SM_INV + s] = __fdividef(1.f, sum);
                }
                asm volatile("bar.sync 1, 128;" ::: "memory");

                // D': ctx over all 10 s per thread, scale by inv at end
                {
                    float cx[S];
#pragma unroll
                    for (int s = 0; s < S; ++s) cx[s] = 0.f;
                    const float* pvb = g_pv + ((long long)b * T * S) * H + k;
#pragma unroll 4
                    for (int tp = 0; tp < t; ++tp) {
                        const float4 pa = *(const float4*)(sm + SM_SSM + tp * 12);
                        const float4 pbv = *(const float4*)(sm + SM_SSM + tp * 12 + 4);
                        const float2 pc = *(const float2*)(sm + SM_SSM + tp * 12 + 8);
                        const float* pvr = pvb + (long long)tp * S * H;
                        cx[0] += pa.x * pvr[0];
                        cx[1] += pa.y * pvr[H];
                        cx[2] += pa.z * pvr[2 * H];
                        cx[3] += pa.w * pvr[3 * H];
                        cx[4] += pbv.x * pvr[4 * H];
                        cx[5] += pbv.y * pvr[5 * H];
                        cx[6] += pbv.z * pvr[6 * H];
                        cx[7] += pbv.w * pvr[7 * H];
                        cx[8] += pc.x * pvr[8 * H];
                        cx[9] += pc.y * pvr[9 * H];
                    }
#pragma unroll
                    for (int s = 0; s < S; ++s)
                        bufT[k * 12 + s] = cx[s] * sm[SM_INV + s];
                }
                asm volatile("bar.sync 1, 128;" ::: "memory");

                // at-GEMM: at = ctx @ W3 + b3 -> ATS
                {
                    u64 At[5];
#pragma unroll
                    for (int p = 0; p < 5; ++p) At[p] = dup2(b3v);
#pragma unroll 8
                    for (int h = 0; h < H; ++h) {
                        const u64 w3 = dup2(sm[SM_W3 + h * H + k]);
                        const float* br = bufT + h * 12;
                        const float4 ba4 = *(const float4*)(br);
                        const float4 bb4 = *(const float4*)(br + 4);
                        const float2 bc2 = *(const float2*)(br + 8);
                        fma2(At[0], pk2(ba4.x, ba4.y), w3);
                        fma2(At[1], pk2(ba4.z, ba4.w), w3);
                        fma2(At[2], pk2(bb4.x, bb4.y), w3);
                        fma2(At[3], pk2(bb4.z, bb4.w), w3);
                        fma2(At[4], pk2(bc2.x, bc2.y), w3);
                    }
#pragma unroll
                    for (int p = 0; p < 5; ++p) {
                        float v0, v1; un2(At[p], v0, v1);
                        sm[SM_ATS + (2 * p) * H + k] = v0;
                        sm[SM_ATS + (2 * p + 1) * H + k] = v1;
                    }
                }
            }
            // prefetch qp(t+1) into the other buffer
            {
                const int tn = t + 1;
                if (tn < kl) {
                    const float* qpp = g_qp + ((long long)(b * T + tn) * S) * H;
                    float* dst = sm + SM_QPS + (tn & 1) * (S * H);
#pragma unroll
                    for (int s = 0; s < S; ++s) dst[s * H + k] = qpp[s * H + k];
                }
            }
        } else {
            // ---------- gate warps: A prefetch + 4-gate GEMM ----------
            {
                const float* Ab = g_A + (((long long)(b * T + t)) * H + k) * 6;
                const float2 x01 = *(const float2*)(Ab);
                const float2 x23 = *(const float2*)(Ab + 2);
                const float2 x45 = *(const float2*)(Ab + 4);
                a0 = x01.x; a1 = x01.y; a2 = x23.x; a3 = x23.y;
                td1 = x45.x; td2 = x45.y;
            }
#pragma unroll
            for (int p = 0; p < 5; ++p) { A0[p] = 0ull; A1[p] = 0ull; A2[p] = 0ull; A3[p] = 0ull; }
            const float2* W01 = g_Wh01 + k;
            const float2* W23 = g_Wh23 + k;
#pragma unroll 8
            for (int h = 0; h < H; ++h) {
                const float2 w01 = W01[h * H];
                const float2 w23 = W23[h * H];
                const u64 w0 = dup2(w01.x), w1 = dup2(w01.y);
                const u64 w2 = dup2(w23.x), w3 = dup2(w23.y);
                const float* hr = hT + h * 12;
                const float4 ha = *(const float4*)(hr);
                const float4 hb = *(const float4*)(hr + 4);
                const float2 hc = *(const float2*)(hr + 8);
                u64 hp[5];
                hp[0] = pk2(ha.x, ha.y); hp[1] = pk2(ha.z, ha.w);
                hp[2] = pk2(hb.x, hb.y); hp[3] = pk2(hb.z, hb.w);
                hp[4] = pk2(hc.x, hc.y);
#pragma unroll
                for (int p = 0; p < 5; ++p) {
                    fma2(A0[p], hp[p], w0); fma2(A1[p], hp[p], w1);
                    fma2(A2[p], hp[p], w2); fma2(A3[p], hp[p], w3);
                }
            }
        }
        __syncthreads();            // gates in regs, ATS ready

        // ===================== cell (wg1) =====================
        if (wg == 1) {
            float G0[S], G1[S], G2[S], G3[S];
#pragma unroll
            for (int p = 0; p < 5; ++p) {
                un2(A0[p], G0[2 * p], G0[2 * p + 1]);
                un2(A1[p], G1[2 * p], G1[2 * p + 1]);
                un2(A2[p], G2[2 * p], G2[2 * p + 1]);
                un2(A3[p], G3[2 * p], G3[2 * p + 1]);
            }
#pragma unroll
            for (int s = 0; s < S; ++s) {
                const float atv = (t > 0) ? sm[SM_ATS + s * H + k] : 1.f;
                const float it = sigf(a0 + G0[s]);
                const float ft = sigf(a1 + G1[s]);
                const float ct = tanhfast(a2 + G2[s]);
                const float ot = sigf(a3 + G3[s]);
                const float itp = it * atv, ftp = ft * atv;
                const float fc = ftp * c[s];
                const float ic = itp * ct;
                const float chat = fc + ic * td1;
                c[s] = fc + ic * td2;
                hT[k * 12 + s] = ot * tanhfast(chat);
            }
        }
        __syncthreads();            // hT(t) ready

        // ===================== G: pk (wg0) / pv + out (wg1) =====================
        if (wg == 0) {
            u64 P[5];
#pragma unroll
            for (int p = 0; p < 5; ++p) P[p] = dup2(b1v);
#pragma unroll 8
            for (int h = 0; h < H; ++h) {
                const u64 w = dup2(sm[SM_W1 + h * H + k]);
                const float* hr = hT + h * 12;
                const float4 ha = *(const float4*)(hr);
                const float4 hb = *(const float4*)(hr + 4);
                const float2 hc = *(const float2*)(hr + 8);
                fma2(P[0], pk2(ha.x, ha.y), w);
                fma2(P[1], pk2(ha.z, ha.w), w);
                fma2(P[2], pk2(hb.x, hb.y), w);
                fma2(P[3], pk2(hb.z, hb.w), w);
                fma2(P[4], pk2(hc.x, hc.y), w);
            }
            float* pkp = g_pk + ((long long)((b * T + t) * S)) * H + k;
#pragma unroll
            for (int p = 0; p < 5; ++p) {
                float v0, v1; un2(P[p], v0, v1);
                pkp[(2 * p) * H] = v0; pkp[(2 * p + 1) * H] = v1;
            }
        } else {
            u64 P[5];
#pragma unroll
            for (int p = 0; p < 5; ++p) P[p] = dup2(b2v);
#pragma unroll 8
            for (int h = 0; h < H; ++h) {
                const u64 w = dup2(sm[SM_W2 + h * H + k]);
                const float* hr = hT + h * 12;
                const float4 ha = *(const float4*)(hr);
                const float4 hb = *(const float4*)(hr + 4);
                const float2 hc = *(const float2*)(hr + 8);
                fma2(P[0], pk2(ha.x, ha.y), w);
                fma2(P[1], pk2(ha.z, ha.w), w);
                fma2(P[2], pk2(hb.x, hb.y), w);
                fma2(P[3], pk2(hb.z, hb.w), w);
                fma2(P[4], pk2(hc.x, hc.y), w);
            }
            float* pvp = g_pv + ((long long)((b * T + t) * S)) * H + k;
#pragma unroll
            for (int p = 0; p < 5; ++p) {
                float v0, v1; un2(P[p], v0, v1);
                pvp[(2 * p) * H] = v0; pvp[(2 * p + 1) * H] = v1;
            }
            float* outp = out + ((long long)((b * T + t) * S)) * H + k;
#pragma unroll
            for (int s = 0; s < S; ++s) outp[s * H] = hT[k * 12 + s];
        }
        __syncthreads();            // pk/pv(t) visible for B'(t+1)
    }

    // masked steps: zeros
    for (; t < T; ++t) {
        float* outp = out + ((long long)((b * T + t) * S)) * H + k;
#pragma unroll
        for (int j = 0; j < 5; ++j) outp[(wg * 5 + j) * H] = 0.f;
    }

    // final h, c (wg1 holds c)
    if (wg == 1) {
        float* oh = out + HSEQ_ELEMS + ((long long)b * S) * H + k;
#pragma unroll
        for (int s = 0; s < S; ++s) oh[s * H] = hT[k * 12 + s];
        float* oc = oh + HC_ELEMS;
#pragma unroll
        for (int s = 0; s < S; ++s) oc[s * H] = c[s];
    }
}

// ---------------- bce: loss from hseq (parallel post-pass) ----------------
__global__ void __launch_bounds__(128) bce_kernel(
    const float* __restrict__ out, const float* __restrict__ austgn_y,
    const int* __restrict__ keys_length)
{
    const int bt = blockIdx.x;
    const int b = bt >> 6, t = bt & 63;
    const int k = threadIdx.x;
    __shared__ float red[4];
    if (t >= keys_length[b]) {
        if (k == 0) g_lpart[bt] = 0.f;
        return;
    }
    const float y = austgn_y[bt];
    const float* hp = out + ((long long)bt * S) * H + k;
    float bsum = 0.f;
#pragma unroll
    for (int s = 0; s < S; ++s) {
        const float hn = hp[s * H];
        const float p = fminf(fmaxf(hn, 1e-7f), 1.f - 1e-7f);
        bsum += -(y * __logf(p) + (1.f - y) * __logf(1.f - p));
    }
#pragma unroll
    for (int o = 16; o > 0; o >>= 1) bsum += __shfl_xor_sync(0xffffffffu, bsum, o);
    if ((k & 31) == 0) red[k >> 5] = bsum;
    __syncthreads();
    if (k == 0)
        g_lpart[bt] = (red[0] + red[1] + red[2] + red[3]) * g_nvinv[t] * (1.f / (float)(S * H));
}

// ---------------- final deterministic loss reduction ----------------
__global__ void __launch_bounds__(256) loss_kernel(float* __restrict__ out)
{
    __shared__ float smr[256];
    const int i = threadIdx.x;
    float sum = 0.f;
    for (int j = 0; j < 64; ++j) sum += g_lpart[i * 64 + j];
    smr[i] = sum;
    __syncthreads();
    for (int off = 128; off > 0; off >>= 1) {
        if (i < off) smr[i] += smr[i + off];
        __syncthreads();
    }
    if (i == 0) out[HSEQ_ELEMS + 2 * HC_ELEMS] = smr[0];
}

// ---------------- launch ----------------
extern "C" void kernel_launch(void* const* d_in, const int* in_sizes, int n_in,
                              void* d_out, int out_size)
{
    (void)in_sizes; (void)n_in; (void)out_size;
    const float* inputs      = (const float*)d_in[0];
    const float* x_q         = (const float*)d_in[1];
    const float* austgn_y    = (const float*)d_in[2];
    const int*   keys_length = (const int*)  d_in[3];
    const float* Wx          = (const float*)d_in[4];
    const float* Wh          = (const float*)d_in[5];
    const float* Wts         = (const float*)d_in[6];
    const float* bg          = (const float*)d_in[7];
    const float* Wa          = (const float*)d_in[8];
    const float* ba          = (const float*)d_in[9];
    const float* Wattn       = (const float*)d_in[10];
    const float* battn       = (const float*)d_in[11];
    float* out = (float*)d_out;

    static int smem_set = 0;
    if (!smem_set) {
        cudaFuncSetAttribute(rec_kernel, cudaFuncAttributeMaxDynamicSharedMemorySize,
                             SM_TOTAL * (int)sizeof(float));
        smem_set = 1;
    }

    fold_kernel<<<256, 128>>>(Wa, ba, Wattn, battn, Wh, keys_length);
    pre_kernel<<<B, 128>>>(inputs, Wx, Wts, bg, keys_length);
    qp_kernel<<<B * T, 128>>>(x_q, keys_length);
    rec_kernel<<<B, 256, SM_TOTAL * (int)sizeof(float)>>>(
        Wattn, battn, keys_length, out);
    bce_kernel<<<B * T, 128>>>(out, austgn_y, keys_length);
    loss_kernel<<<1, 256>>>(out);
}